// round 3
// baseline (speedup 1.0000x reference)
#include <cuda_runtime.h>

// Problem constants (fixed by setup_inputs)
#define BB 2
#define GG 16
#define N1 4096
#define S1 1024
#define NTOT 65536   // GG*N1
#define STOT 16384   // GG*S1
#define D1 128
#define D2 256
#define C1 256
#define C2 256
#define INCH 384
#define BN_CNT 8192  // BB*N1 samples per (segment, channel)

// -------- device scratch (no allocations allowed) --------
__device__ float g_Y2t[BB * GG][S1][C1];       // 33.5 MB: (W1b @ p2)^T per segment
__device__ int   g_idx[BB * GG][N1][3];        // 1.5 MB
__device__ float g_w[BB * GG][N1][3];          // 1.5 MB
__device__ float g_h1[BB][C1][NTOT];           // 134 MB: layer-1 pre-activation
__device__ float g_scale1[GG][C1];
__device__ float g_shift1[GG][C1];
__device__ float g_scale2[GG][C2];
__device__ float g_shift2[GG][C2];

// ============================================================
// K1: 3-NN + inverse-distance weights.
// grid = (N1/256, B*G), block = 256. Sources staged in smem.
// ============================================================
__global__ __launch_bounds__(256) void knn_kernel(
    const float* __restrict__ xyz1, const float* __restrict__ xyz2)
{
    __shared__ float sx[S1], sy[S1], sz[S1];
    const int bg = blockIdx.y;
    const int b = bg >> 4, g = bg & 15;
    const float* x2 = xyz2 + (size_t)b * 3 * STOT + g * S1;
    for (int s = threadIdx.x; s < S1; s += 256) {
        sx[s] = x2[s];
        sy[s] = x2[STOT + s];
        sz[s] = x2[2 * STOT + s];
    }
    __syncthreads();

    const int n = blockIdx.x * 256 + threadIdx.x;
    const float* x1 = xyz1 + (size_t)b * 3 * NTOT + g * N1 + n;
    const float qx = x1[0], qy = x1[NTOT], qz = x1[2 * NTOT];

    float d0 = 3.4e38f, d1 = 3.4e38f, d2 = 3.4e38f;
    int i0 = 0, i1 = 0, i2 = 0;
    #pragma unroll 4
    for (int s = 0; s < S1; s++) {
        const float dx = qx - sx[s];
        const float dy = qy - sy[s];
        const float dz = qz - sz[s];
        const float d = fmaf(dx, dx, fmaf(dy, dy, dz * dz));
        if (d < d2) {
            if (d < d1) {
                if (d < d0) { d2 = d1; i2 = i1; d1 = d0; i1 = i0; d0 = d; i0 = s; }
                else        { d2 = d1; i2 = i1; d1 = d;  i1 = s; }
            } else          { d2 = d;  i2 = s; }
        }
    }
    float w0 = 1.0f / (d0 + 1e-8f);
    float w1 = 1.0f / (d1 + 1e-8f);
    float w2 = 1.0f / (d2 + 1e-8f);
    const float inv = 1.0f / (w0 + w1 + w2);
    g_idx[bg][n][0] = i0; g_idx[bg][n][1] = i1; g_idx[bg][n][2] = i2;
    g_w[bg][n][0] = w0 * inv; g_w[bg][n][1] = w1 * inv; g_w[bg][n][2] = w2 * inv;
}

// ============================================================
// K2: Y2t[bg][s][o] = sum_c p2[b][c][gS1+s] * W1[o][128+c]
// Tiled SGEMM: block 64(m=s) x 64(n=o), K-tile 16, 256 threads, 4x4 micro.
// grid = (S1/64=16, C1/64=4, 32)
// ============================================================
__global__ __launch_bounds__(256) void y2t_kernel(
    const float* __restrict__ p2, const float* __restrict__ W1)
{
    __shared__ float As[16][64];
    __shared__ float Bs[16][68];
    const int m0 = blockIdx.x * 64;
    const int n0 = blockIdx.y * 64;
    const int bg = blockIdx.z, b = bg >> 4, g = bg & 15;
    const int tid = threadIdx.x;
    const int tx = tid & 15, ty = tid >> 4;

    const float* Abase = p2 + (size_t)b * D2 * STOT + (size_t)g * S1 + m0;
    const float* Bbase = W1 + 128;  // W1b columns
    const int arow = tid >> 4, acol = (tid & 15) * 4;
    const int brow = tid >> 2, bk4 = (tid & 3) * 4;

    float acc[4][4] = {};
    for (int kt = 0; kt < 256; kt += 16) {
        float4 av = *(const float4*)(Abase + (size_t)(kt + arow) * STOT + acol);
        *(float4*)&As[arow][acol] = av;
        float4 bv = *(const float4*)(Bbase + (size_t)(n0 + brow) * INCH + kt + bk4);
        Bs[bk4 + 0][brow] = bv.x; Bs[bk4 + 1][brow] = bv.y;
        Bs[bk4 + 2][brow] = bv.z; Bs[bk4 + 3][brow] = bv.w;
        __syncthreads();
        #pragma unroll
        for (int k = 0; k < 16; k++) {
            const float4 a4 = *(const float4*)&As[k][ty * 4];
            const float4 w4 = *(const float4*)&Bs[k][tx * 4];
            const float a[4] = {a4.x, a4.y, a4.z, a4.w};
            const float w[4] = {w4.x, w4.y, w4.z, w4.w};
            #pragma unroll
            for (int i = 0; i < 4; i++)
                #pragma unroll
                for (int j = 0; j < 4; j++)
                    acc[i][j] = fmaf(a[i], w[j], acc[i][j]);
        }
        __syncthreads();
    }
    #pragma unroll
    for (int i = 0; i < 4; i++) {
        const int s = m0 + ty * 4 + i;
        float4 v = make_float4(acc[i][0], acc[i][1], acc[i][2], acc[i][3]);
        *(float4*)&g_Y2t[bg][s][n0 + tx * 4] = v;
    }
}

// ============================================================
// K3: h1_pre[b][o][gN1+n] = sum_{c<128} W1[o][c]*p1[b][c][gN1+n]
//                         + sum_k w_k * Y2t[bg][idx_k][o] + b1[o]
// grid = (N1/64=64, C1/64=4, 32)
// ============================================================
__global__ __launch_bounds__(256) void h1_kernel(
    const float* __restrict__ p1, const float* __restrict__ W1,
    const float* __restrict__ b1)
{
    __shared__ float As[16][64];
    __shared__ float Bs[16][68];
    const int m0 = blockIdx.x * 64;
    const int n0 = blockIdx.y * 64;
    const int bg = blockIdx.z, b = bg >> 4, g = bg & 15;
    const int tid = threadIdx.x;
    const int tx = tid & 15, ty = tid >> 4;

    const float* Abase = p1 + (size_t)b * D1 * NTOT + (size_t)g * N1 + m0;
    const int arow = tid >> 4, acol = (tid & 15) * 4;
    const int brow = tid >> 2, bk4 = (tid & 3) * 4;

    float acc[4][4] = {};
    for (int kt = 0; kt < 128; kt += 16) {
        float4 av = *(const float4*)(Abase + (size_t)(kt + arow) * NTOT + acol);
        *(float4*)&As[arow][acol] = av;
        float4 bv = *(const float4*)(W1 + (size_t)(n0 + brow) * INCH + kt + bk4);
        Bs[bk4 + 0][brow] = bv.x; Bs[bk4 + 1][brow] = bv.y;
        Bs[bk4 + 2][brow] = bv.z; Bs[bk4 + 3][brow] = bv.w;
        __syncthreads();
        #pragma unroll
        for (int k = 0; k < 16; k++) {
            const float4 a4 = *(const float4*)&As[k][ty * 4];
            const float4 w4 = *(const float4*)&Bs[k][tx * 4];
            const float a[4] = {a4.x, a4.y, a4.z, a4.w};
            const float w[4] = {w4.x, w4.y, w4.z, w4.w};
            #pragma unroll
            for (int i = 0; i < 4; i++)
                #pragma unroll
                for (int j = 0; j < 4; j++)
                    acc[i][j] = fmaf(a[i], w[j], acc[i][j]);
        }
        __syncthreads();
    }

    // Interpolation gather (pushed past the GEMM) + bias
    const float4 bias = *(const float4*)(b1 + n0 + tx * 4);
    #pragma unroll
    for (int i = 0; i < 4; i++) {
        const int m = m0 + ty * 4 + i;
        #pragma unroll
        for (int k = 0; k < 3; k++) {
            const int s = g_idx[bg][m][k];
            const float wk = g_w[bg][m][k];
            const float4 y = *(const float4*)&g_Y2t[bg][s][n0 + tx * 4];
            acc[i][0] = fmaf(wk, y.x, acc[i][0]);
            acc[i][1] = fmaf(wk, y.y, acc[i][1]);
            acc[i][2] = fmaf(wk, y.z, acc[i][2]);
            acc[i][3] = fmaf(wk, y.w, acc[i][3]);
        }
        acc[i][0] += bias.x; acc[i][1] += bias.y;
        acc[i][2] += bias.z; acc[i][3] += bias.w;
    }

    // Store: channel-major layout, float4 along m
    #pragma unroll
    for (int j = 0; j < 4; j++) {
        const int o = n0 + tx * 4 + j;
        float4 v = make_float4(acc[0][j], acc[1][j], acc[2][j], acc[3][j]);
        *(float4*)&g_h1[b][o][g * N1 + m0 + ty * 4] = v;
    }
}

// ============================================================
// K4/K6: per-(segment, channel) BN stats -> (scale, shift).
// grid = (C, G), block = 256. layer=0 reads g_h1, layer=1 reads x2 (=d_out).
// ============================================================
__global__ __launch_bounds__(256) void bnstats_kernel(
    const float* __restrict__ x2, const float* __restrict__ gamma,
    const float* __restrict__ beta, int layer)
{
    const int c = blockIdx.x, g = blockIdx.y, tid = threadIdx.x;
    const float* x = layer ? x2 : &g_h1[0][0][0];
    float s = 0.f, q = 0.f;
    for (int b = 0; b < BB; b++) {
        const float4* p = (const float4*)(x + ((size_t)(b * 256 + c)) * NTOT + (size_t)g * N1);
        for (int t = tid; t < N1 / 4; t += 256) {
            const float4 v = p[t];
            s += (v.x + v.y) + (v.z + v.w);
            q = fmaf(v.x, v.x, q); q = fmaf(v.y, v.y, q);
            q = fmaf(v.z, v.z, q); q = fmaf(v.w, v.w, q);
        }
    }
    __shared__ float rs[256], rq[256];
    rs[tid] = s; rq[tid] = q;
    __syncthreads();
    for (int off = 128; off; off >>= 1) {
        if (tid < off) { rs[tid] += rs[tid + off]; rq[tid] += rq[tid + off]; }
        __syncthreads();
    }
    if (tid == 0) {
        const float inv = 1.0f / (float)BN_CNT;
        const float mean = rs[0] * inv;
        const float var = rq[0] * inv - mean * mean;
        const float sc = gamma[c] * rsqrtf(var + 1e-5f);
        const float sh = beta[c] - mean * sc;
        if (layer == 0) { g_scale1[g][c] = sc; g_shift1[g][c] = sh; }
        else            { g_scale2[g][c] = sc; g_shift2[g][c] = sh; }
    }
}

// ============================================================
// K5: h2_pre = W2 @ relu(bn1(h1_pre)) + b2, written into d_out.
// BN1+ReLU fused into the A-tile smem store. grid = (64, 4, 32)
// ============================================================
__global__ __launch_bounds__(256) void gemm2_kernel(
    const float* __restrict__ W2, const float* __restrict__ b2,
    float* __restrict__ out)
{
    __shared__ float As[16][64];
    __shared__ float Bs[16][68];
    const int m0 = blockIdx.x * 64;
    const int n0 = blockIdx.y * 64;
    const int bg = blockIdx.z, b = bg >> 4, g = bg & 15;
    const int tid = threadIdx.x;
    const int tx = tid & 15, ty = tid >> 4;

    const float* Abase = &g_h1[b][0][g * N1 + m0];
    const int arow = tid >> 4, acol = (tid & 15) * 4;
    const int brow = tid >> 2, bk4 = (tid & 3) * 4;

    float acc[4][4] = {};
    for (int kt = 0; kt < 256; kt += 16) {
        const int c = kt + arow;
        const float sc = g_scale1[g][c];
        const float sh = g_shift1[g][c];
        float4 av = *(const float4*)(Abase + (size_t)c * NTOT + acol);
        av.x = fmaxf(fmaf(av.x, sc, sh), 0.f);
        av.y = fmaxf(fmaf(av.y, sc, sh), 0.f);
        av.z = fmaxf(fmaf(av.z, sc, sh), 0.f);
        av.w = fmaxf(fmaf(av.w, sc, sh), 0.f);
        *(float4*)&As[arow][acol] = av;
        float4 bv = *(const float4*)(W2 + (size_t)(n0 + brow) * 256 + kt + bk4);
        Bs[bk4 + 0][brow] = bv.x; Bs[bk4 + 1][brow] = bv.y;
        Bs[bk4 + 2][brow] = bv.z; Bs[bk4 + 3][brow] = bv.w;
        __syncthreads();
        #pragma unroll
        for (int k = 0; k < 16; k++) {
            const float4 a4 = *(const float4*)&As[k][ty * 4];
            const float4 w4 = *(const float4*)&Bs[k][tx * 4];
            const float a[4] = {a4.x, a4.y, a4.z, a4.w};
            const float w[4] = {w4.x, w4.y, w4.z, w4.w};
            #pragma unroll
            for (int i = 0; i < 4; i++)
                #pragma unroll
                for (int j = 0; j < 4; j++)
                    acc[i][j] = fmaf(a[i], w[j], acc[i][j]);
        }
        __syncthreads();
    }
    const float4 bias = *(const float4*)(b2 + n0 + tx * 4);
    #pragma unroll
    for (int j = 0; j < 4; j++) {
        const int o = n0 + tx * 4 + j;
        const float bj = (j == 0) ? bias.x : (j == 1) ? bias.y : (j == 2) ? bias.z : bias.w;
        float4 v = make_float4(acc[0][j] + bj, acc[1][j] + bj, acc[2][j] + bj, acc[3][j] + bj);
        *(float4*)(out + ((size_t)(b * 256 + o)) * NTOT + g * N1 + m0 + ty * 4) = v;
    }
}

// ============================================================
// K7: in-place BN2 + ReLU on d_out. grid = 32768 blocks * 256, float4.
// flat float index f: b = f>>24, o = (f>>16)&255, g = (f>>12)&15
// ============================================================
__global__ __launch_bounds__(256) void bnfinal_kernel(float* __restrict__ out)
{
    const size_t f4 = (size_t)blockIdx.x * 256 + threadIdx.x;
    const size_t f = f4 * 4;
    const int o = (int)((f >> 16) & 255);
    const int g = (int)((f >> 12) & 15);
    const float sc = g_scale2[g][o];
    const float sh = g_shift2[g][o];
    float4 v = ((float4*)out)[f4];
    v.x = fmaxf(fmaf(v.x, sc, sh), 0.f);
    v.y = fmaxf(fmaf(v.y, sc, sh), 0.f);
    v.z = fmaxf(fmaf(v.z, sc, sh), 0.f);
    v.w = fmaxf(fmaf(v.w, sc, sh), 0.f);
    ((float4*)out)[f4] = v;
}

// ============================================================
extern "C" void kernel_launch(void* const* d_in, const int* in_sizes, int n_in,
                              void* d_out, int out_size)
{
    (void)in_sizes; (void)n_in; (void)out_size;
    const float* xyz1    = (const float*)d_in[0];
    const float* points1 = (const float*)d_in[1];
    const float* xyz2    = (const float*)d_in[3];
    const float* points2 = (const float*)d_in[4];
    const float* W1      = (const float*)d_in[6];
    const float* b1      = (const float*)d_in[7];
    const float* gamma1  = (const float*)d_in[8];
    const float* beta1   = (const float*)d_in[9];
    const float* W2      = (const float*)d_in[10];
    const float* b2      = (const float*)d_in[11];
    const float* gamma2  = (const float*)d_in[12];
    const float* beta2   = (const float*)d_in[13];
    float* out = (float*)d_out;

    knn_kernel<<<dim3(N1 / 256, BB * GG), 256>>>(xyz1, xyz2);
    y2t_kernel<<<dim3(S1 / 64, C1 / 64, BB * GG), 256>>>(points2, W1);
    h1_kernel<<<dim3(N1 / 64, C1 / 64, BB * GG), 256>>>(points1, W1, b1);
    bnstats_kernel<<<dim3(C1, GG), 256>>>(nullptr, gamma1, beta1, 0);
    gemm2_kernel<<<dim3(N1 / 64, C2 / 64, BB * GG), 256>>>(W2, b2, out);
    bnstats_kernel<<<dim3(C2, GG), 256>>>(out, gamma2, beta2, 1);
    bnfinal_kernel<<<(BB * C2 * NTOT) / 4 / 256, 256>>>(out);
}

// round 6
// speedup vs baseline: 2.0451x; 2.0451x over previous
#include <cuda_runtime.h>
#include <cstdint>

// Problem constants (fixed by setup_inputs)
#define BB 2
#define GG 16
#define N1 4096
#define S1 1024
#define NTOT 65536   // GG*N1
#define STOT 16384   // GG*S1
#define D1 128
#define D2 256
#define C1 256
#define C2 256
#define INCH 384
#define BN_CNT 8192  // BB*N1 samples per (segment, channel)

// -------- device scratch (no allocations allowed) --------
__device__ float g_Y2t[BB * GG][S1][C1];       // 33.5 MB: (W1b @ p2)^T per segment
__device__ int   g_idx[BB * GG][N1][3];
__device__ float g_w[BB * GG][N1][3];
__device__ float g_h1[BB][C1][NTOT];           // 134 MB: layer-1 pre-activation
__device__ float g_scale1[GG][C1];
__device__ float g_shift1[GG][C1];
__device__ float g_scale2[GG][C2];
__device__ float g_shift2[GG][C2];

// -------- tf32 helpers --------
__device__ __forceinline__ uint32_t f2tf(float x) {
    uint32_t u;
    asm("cvt.rna.tf32.f32 %0, %1;" : "=r"(u) : "f"(x));
    return u;
}

__device__ __forceinline__ void mma8(float& c0, float& c1, float& c2, float& c3,
                                     uint32_t a0, uint32_t a1, uint32_t a2, uint32_t a3,
                                     uint32_t b0, uint32_t b1) {
    asm volatile(
        "mma.sync.aligned.m16n8k8.row.col.f32.tf32.tf32.f32 "
        "{%0,%1,%2,%3},{%4,%5,%6,%7},{%8,%9},{%0,%1,%2,%3};"
        : "+f"(c0), "+f"(c1), "+f"(c2), "+f"(c3)
        : "r"(a0), "r"(a1), "r"(a2), "r"(a3), "r"(b0), "r"(b1));
}

// Shared-tile MMA core: BM=128 x BN=128 x BK=16, 8 warps (2 m x 4 n),
// warp tile 64x32 = 4x4 m16n8k8 tiles. As[k][m] pitch 136, Bs[n][k] pitch 20
// (both conflict-free for the fragment access patterns).
__device__ __forceinline__ void compute_tile(
    const uint32_t (*As)[136], const uint32_t (*Bs)[20],
    float acc[4][4][4], int wm, int wn, int g, int tg)
{
    #pragma unroll
    for (int kk = 0; kk < 16; kk += 8) {
        uint32_t af[4][4];
        #pragma unroll
        for (int i = 0; i < 4; i++) {
            const int m = wm * 64 + i * 16 + g;
            af[i][0] = As[kk + tg][m];
            af[i][1] = As[kk + tg][m + 8];
            af[i][2] = As[kk + tg + 4][m];
            af[i][3] = As[kk + tg + 4][m + 8];
        }
        #pragma unroll
        for (int j = 0; j < 4; j++) {
            const int n = wn * 32 + j * 8 + g;
            const uint32_t b0 = Bs[n][kk + tg];
            const uint32_t b1 = Bs[n][kk + tg + 4];
            #pragma unroll
            for (int i = 0; i < 4; i++)
                mma8(acc[i][j][0], acc[i][j][1], acc[i][j][2], acc[i][j][3],
                     af[i][0], af[i][1], af[i][2], af[i][3], b0, b1);
        }
    }
}

// ============================================================
// K1: 3-NN + inverse-distance weights (fp32).
// ============================================================
__global__ __launch_bounds__(256) void knn_kernel(
    const float* __restrict__ xyz1, const float* __restrict__ xyz2)
{
    __shared__ float sx[S1], sy[S1], sz[S1];
    const int bg = blockIdx.y;
    const int b = bg >> 4, g = bg & 15;
    const float* x2 = xyz2 + (size_t)b * 3 * STOT + g * S1;
    for (int s = threadIdx.x; s < S1; s += 256) {
        sx[s] = x2[s];
        sy[s] = x2[STOT + s];
        sz[s] = x2[2 * STOT + s];
    }
    __syncthreads();

    const int n = blockIdx.x * 256 + threadIdx.x;
    const float* x1 = xyz1 + (size_t)b * 3 * NTOT + g * N1 + n;
    const float qx = x1[0], qy = x1[NTOT], qz = x1[2 * NTOT];

    float d0 = 3.4e38f, d1 = 3.4e38f, d2 = 3.4e38f;
    int i0 = 0, i1 = 0, i2 = 0;
    #pragma unroll 4
    for (int s = 0; s < S1; s++) {
        const float dx = qx - sx[s];
        const float dy = qy - sy[s];
        const float dz = qz - sz[s];
        const float d = fmaf(dx, dx, fmaf(dy, dy, dz * dz));
        if (d < d2) {
            if (d < d1) {
                if (d < d0) { d2 = d1; i2 = i1; d1 = d0; i1 = i0; d0 = d; i0 = s; }
                else        { d2 = d1; i2 = i1; d1 = d;  i1 = s; }
            } else          { d2 = d;  i2 = s; }
        }
    }
    float w0 = 1.0f / (d0 + 1e-8f);
    float w1 = 1.0f / (d1 + 1e-8f);
    float w2 = 1.0f / (d2 + 1e-8f);
    const float inv = 1.0f / (w0 + w1 + w2);
    g_idx[bg][n][0] = i0; g_idx[bg][n][1] = i1; g_idx[bg][n][2] = i2;
    g_w[bg][n][0] = w0 * inv; g_w[bg][n][1] = w1 * inv; g_w[bg][n][2] = w2 * inv;
}

// ============================================================
// K2: Y2t[bg][s][o] = sum_c p2[b][c][gS1+s] * W1[o][128+c]   (tf32 MMA)
// grid = (S1/128=8, C1/128=2, 32)
// ============================================================
__global__ __launch_bounds__(256, 2) void y2t_mma(
    const float* __restrict__ p2, const float* __restrict__ W1)
{
    __shared__ uint32_t As[16][136];
    __shared__ uint32_t Bs[128][20];
    const int m0 = blockIdx.x * 128, n0 = blockIdx.y * 128;
    const int bg = blockIdx.z, b = bg >> 4, gg = bg & 15;
    const int tid = threadIdx.x, lane = tid & 31, wid = tid >> 5;
    const int wm = wid & 1, wn = wid >> 1, g = lane >> 2, tg = lane & 3;

    const float* Ab = p2 + (size_t)b * D2 * STOT + gg * S1 + m0;
    const float* Bb = W1 + 128 + (size_t)n0 * INCH;

    float acc[4][4][4] = {};
    float4 pa[2], pb[2];
    #pragma unroll
    for (int it = 0; it < 2; it++) {
        const int idx = tid + it * 256;
        pa[it] = *(const float4*)(Ab + (size_t)(idx >> 5) * STOT + (idx & 31) * 4);
        pb[it] = *(const float4*)(Bb + (size_t)(idx >> 2) * INCH + (idx & 3) * 4);
    }
    for (int kt = 0; kt < 256; kt += 16) {
        __syncthreads();
        #pragma unroll
        for (int it = 0; it < 2; it++) {
            const int idx = tid + it * 256;
            *(uint4*)&As[idx >> 5][(idx & 31) * 4] =
                make_uint4(f2tf(pa[it].x), f2tf(pa[it].y), f2tf(pa[it].z), f2tf(pa[it].w));
            *(uint4*)&Bs[idx >> 2][(idx & 3) * 4] =
                make_uint4(f2tf(pb[it].x), f2tf(pb[it].y), f2tf(pb[it].z), f2tf(pb[it].w));
        }
        __syncthreads();
        if (kt + 16 < 256) {
            #pragma unroll
            for (int it = 0; it < 2; it++) {
                const int idx = tid + it * 256;
                pa[it] = *(const float4*)(Ab + (size_t)(kt + 16 + (idx >> 5)) * STOT + (idx & 31) * 4);
                pb[it] = *(const float4*)(Bb + (size_t)(idx >> 2) * INCH + kt + 16 + (idx & 3) * 4);
            }
        }
        compute_tile(As, Bs, acc, wm, wn, g, tg);
    }
    #pragma unroll
    for (int i = 0; i < 4; i++) {
        const int s = m0 + wm * 64 + i * 16 + g;
        #pragma unroll
        for (int j = 0; j < 4; j++) {
            const int o = n0 + wn * 32 + j * 8 + 2 * tg;
            *(float2*)&g_Y2t[bg][s][o]     = make_float2(acc[i][j][0], acc[i][j][1]);
            *(float2*)&g_Y2t[bg][s + 8][o] = make_float2(acc[i][j][2], acc[i][j][3]);
        }
    }
}

// ============================================================
// K3: h1_pre = W1a @ p1 (tf32 MMA, K=128) + fp32 interp-gather + bias.
// grid = (N1/128=32, 2, 32)
// ============================================================
__global__ __launch_bounds__(256, 2) void h1_mma(
    const float* __restrict__ p1, const float* __restrict__ W1,
    const float* __restrict__ b1)
{
    __shared__ uint32_t As[16][136];
    __shared__ uint32_t Bs[128][20];
    const int m0 = blockIdx.x * 128, n0 = blockIdx.y * 128;
    const int bg = blockIdx.z, b = bg >> 4, gg = bg & 15;
    const int tid = threadIdx.x, lane = tid & 31, wid = tid >> 5;
    const int wm = wid & 1, wn = wid >> 1, g = lane >> 2, tg = lane & 3;

    const float* Ab = p1 + (size_t)b * D1 * NTOT + gg * N1 + m0;
    const float* Bb = W1 + (size_t)n0 * INCH;

    float acc[4][4][4] = {};
    float4 pa[2], pb[2];
    #pragma unroll
    for (int it = 0; it < 2; it++) {
        const int idx = tid + it * 256;
        pa[it] = *(const float4*)(Ab + (size_t)(idx >> 5) * NTOT + (idx & 31) * 4);
        pb[it] = *(const float4*)(Bb + (size_t)(idx >> 2) * INCH + (idx & 3) * 4);
    }
    for (int kt = 0; kt < 128; kt += 16) {
        __syncthreads();
        #pragma unroll
        for (int it = 0; it < 2; it++) {
            const int idx = tid + it * 256;
            *(uint4*)&As[idx >> 5][(idx & 31) * 4] =
                make_uint4(f2tf(pa[it].x), f2tf(pa[it].y), f2tf(pa[it].z), f2tf(pa[it].w));
            *(uint4*)&Bs[idx >> 2][(idx & 3) * 4] =
                make_uint4(f2tf(pb[it].x), f2tf(pb[it].y), f2tf(pb[it].z), f2tf(pb[it].w));
        }
        __syncthreads();
        if (kt + 16 < 128) {
            #pragma unroll
            for (int it = 0; it < 2; it++) {
                const int idx = tid + it * 256;
                pa[it] = *(const float4*)(Ab + (size_t)(kt + 16 + (idx >> 5)) * NTOT + (idx & 31) * 4);
                pb[it] = *(const float4*)(Bb + (size_t)(idx >> 2) * INCH + kt + 16 + (idx & 3) * 4);
            }
        }
        compute_tile(As, Bs, acc, wm, wn, g, tg);
    }

    // fp32 epilogue: 3-NN interpolation of precomputed Y2t, + bias, store to g_h1
    #pragma unroll
    for (int i = 0; i < 4; i++) {
        const int rA = m0 + wm * 64 + i * 16 + g;
        const int rB = rA + 8;
        int   iA[3], iB[3];
        float wA[3], wB[3];
        #pragma unroll
        for (int k = 0; k < 3; k++) {
            iA[k] = g_idx[bg][rA][k]; wA[k] = g_w[bg][rA][k];
            iB[k] = g_idx[bg][rB][k]; wB[k] = g_w[bg][rB][k];
        }
        #pragma unroll
        for (int j = 0; j < 4; j++) {
            const int o = n0 + wn * 32 + j * 8 + 2 * tg;
            float c0 = acc[i][j][0], c1 = acc[i][j][1];
            float c2 = acc[i][j][2], c3 = acc[i][j][3];
            #pragma unroll
            for (int k = 0; k < 3; k++) {
                const float2 yA = *(const float2*)&g_Y2t[bg][iA[k]][o];
                c0 = fmaf(wA[k], yA.x, c0); c1 = fmaf(wA[k], yA.y, c1);
                const float2 yB = *(const float2*)&g_Y2t[bg][iB[k]][o];
                c2 = fmaf(wB[k], yB.x, c2); c3 = fmaf(wB[k], yB.y, c3);
            }
            const float2 bo = *(const float2*)(b1 + o);
            g_h1[b][o][gg * N1 + rA]     = c0 + bo.x;
            g_h1[b][o + 1][gg * N1 + rA] = c1 + bo.y;
            g_h1[b][o][gg * N1 + rB]     = c2 + bo.x;
            g_h1[b][o + 1][gg * N1 + rB] = c3 + bo.y;
        }
    }
}

// ============================================================
// K4/K6: per-(segment, channel) BN stats -> (scale, shift).
// ============================================================
__global__ __launch_bounds__(256) void bnstats_kernel(
    const float* __restrict__ x2, const float* __restrict__ gamma,
    const float* __restrict__ beta, int layer)
{
    const int c = blockIdx.x, g = blockIdx.y, tid = threadIdx.x;
    const float* x = layer ? x2 : &g_h1[0][0][0];
    float s = 0.f, q = 0.f;
    for (int b = 0; b < BB; b++) {
        const float4* p = (const float4*)(x + ((size_t)(b * 256 + c)) * NTOT + (size_t)g * N1);
        for (int t = tid; t < N1 / 4; t += 256) {
            const float4 v = p[t];
            s += (v.x + v.y) + (v.z + v.w);
            q = fmaf(v.x, v.x, q); q = fmaf(v.y, v.y, q);
            q = fmaf(v.z, v.z, q); q = fmaf(v.w, v.w, q);
        }
    }
    __shared__ float rs[256], rq[256];
    rs[tid] = s; rq[tid] = q;
    __syncthreads();
    for (int off = 128; off; off >>= 1) {
        if (tid < off) { rs[tid] += rs[tid + off]; rq[tid] += rq[tid + off]; }
        __syncthreads();
    }
    if (tid == 0) {
        const float inv = 1.0f / (float)BN_CNT;
        const float mean = rs[0] * inv;
        const float var = rq[0] * inv - mean * mean;
        const float sc = gamma[c] * rsqrtf(var + 1e-5f);
        const float sh = beta[c] - mean * sc;
        if (layer == 0) { g_scale1[g][c] = sc; g_shift1[g][c] = sh; }
        else            { g_scale2[g][c] = sc; g_shift2[g][c] = sh; }
    }
}

// ============================================================
// K5: h2_pre = W2 @ relu(bn1(h1_pre)) + b2  (tf32 MMA; BN1+ReLU fused
// into A-tile conversion). grid = (32, 2, 32). Writes d_out.
// ============================================================
__global__ __launch_bounds__(256, 2) void gemm2_mma(
    const float* __restrict__ W2, const float* __restrict__ b2,
    float* __restrict__ out)
{
    __shared__ uint32_t As[16][136];
    __shared__ uint32_t Bs[128][20];
    const int m0 = blockIdx.x * 128, n0 = blockIdx.y * 128;
    const int bg = blockIdx.z, b = bg >> 4, gg = bg & 15;
    const int tid = threadIdx.x, lane = tid & 31, wid = tid >> 5;
    const int wm = wid & 1, wn = wid >> 1, g = lane >> 2, tg = lane & 3;

    const float* Ab = &g_h1[b][0][gg * N1 + m0];
    const float* Bb = W2 + (size_t)n0 * 256;

    float acc[4][4][4] = {};
    float4 pa[2], pb[2];
    float psc[2], psh[2];
    #pragma unroll
    for (int it = 0; it < 2; it++) {
        const int idx = tid + it * 256;
        const int kr = idx >> 5;
        pa[it] = *(const float4*)(Ab + (size_t)kr * NTOT + (idx & 31) * 4);
        pb[it] = *(const float4*)(Bb + (size_t)(idx >> 2) * 256 + (idx & 3) * 4);
        psc[it] = g_scale1[gg][kr];
        psh[it] = g_shift1[gg][kr];
    }
    for (int kt = 0; kt < 256; kt += 16) {
        __syncthreads();
        #pragma unroll
        for (int it = 0; it < 2; it++) {
            const int idx = tid + it * 256;
            const float sc = psc[it], sh = psh[it];
            const float vx = fmaxf(fmaf(pa[it].x, sc, sh), 0.f);
            const float vy = fmaxf(fmaf(pa[it].y, sc, sh), 0.f);
            const float vz = fmaxf(fmaf(pa[it].z, sc, sh), 0.f);
            const float vw = fmaxf(fmaf(pa[it].w, sc, sh), 0.f);
            *(uint4*)&As[idx >> 5][(idx & 31) * 4] =
                make_uint4(f2tf(vx), f2tf(vy), f2tf(vz), f2tf(vw));
            *(uint4*)&Bs[idx >> 2][(idx & 3) * 4] =
                make_uint4(f2tf(pb[it].x), f2tf(pb[it].y), f2tf(pb[it].z), f2tf(pb[it].w));
        }
        __syncthreads();
        if (kt + 16 < 256) {
            #pragma unroll
            for (int it = 0; it < 2; it++) {
                const int idx = tid + it * 256;
                const int c = kt + 16 + (idx >> 5);
                pa[it] = *(const float4*)(Ab + (size_t)c * NTOT + (idx & 31) * 4);
                pb[it] = *(const float4*)(Bb + (size_t)(idx >> 2) * 256 + kt + 16 + (idx & 3) * 4);
                psc[it] = g_scale1[gg][c];
                psh[it] = g_shift1[gg][c];
            }
        }
        compute_tile(As, Bs, acc, wm, wn, g, tg);
    }
    #pragma unroll
    for (int i = 0; i < 4; i++) {
        const int rA = m0 + wm * 64 + i * 16 + g;
        const int rB = rA + 8;
        #pragma unroll
        for (int j = 0; j < 4; j++) {
            const int o = n0 + wn * 32 + j * 8 + 2 * tg;
            const float2 bo = *(const float2*)(b2 + o);
            out[((size_t)(b * 256 + o)) * NTOT + gg * N1 + rA]     = acc[i][j][0] + bo.x;
            out[((size_t)(b * 256 + o + 1)) * NTOT + gg * N1 + rA] = acc[i][j][1] + bo.y;
            out[((size_t)(b * 256 + o)) * NTOT + gg * N1 + rB]     = acc[i][j][2] + bo.x;
            out[((size_t)(b * 256 + o + 1)) * NTOT + gg * N1 + rB] = acc[i][j][3] + bo.y;
        }
    }
}

// ============================================================
// K7: in-place BN2 + ReLU on d_out.
// ============================================================
__global__ __launch_bounds__(256) void bnfinal_kernel(float* __restrict__ out)
{
    const size_t f4 = (size_t)blockIdx.x * 256 + threadIdx.x;
    const size_t f = f4 * 4;
    const int o = (int)((f >> 16) & 255);
    const int g = (int)((f >> 12) & 15);
    const float sc = g_scale2[g][o];
    const float sh = g_shift2[g][o];
    float4 v = ((float4*)out)[f4];
    v.x = fmaxf(fmaf(v.x, sc, sh), 0.f);
    v.y = fmaxf(fmaf(v.y, sc, sh), 0.f);
    v.z = fmaxf(fmaf(v.z, sc, sh), 0.f);
    v.w = fmaxf(fmaf(v.w, sc, sh), 0.f);
    ((float4*)out)[f4] = v;
}

// ============================================================
extern "C" void kernel_launch(void* const* d_in, const int* in_sizes, int n_in,
                              void* d_out, int out_size)
{
    (void)in_sizes; (void)n_in; (void)out_size;
    const float* xyz1    = (const float*)d_in[0];
    const float* points1 = (const float*)d_in[1];
    const float* xyz2    = (const float*)d_in[3];
    const float* points2 = (const float*)d_in[4];
    const float* W1      = (const float*)d_in[6];
    const float* b1      = (const float*)d_in[7];
    const float* gamma1  = (const float*)d_in[8];
    const float* beta1   = (const float*)d_in[9];
    const float* W2      = (const float*)d_in[10];
    const float* b2      = (const float*)d_in[11];
    const float* gamma2  = (const float*)d_in[12];
    const float* beta2   = (const float*)d_in[13];
    float* out = (float*)d_out;

    knn_kernel<<<dim3(N1 / 256, BB * GG), 256>>>(xyz1, xyz2);
    y2t_mma<<<dim3(S1 / 128, C1 / 128, BB * GG), 256>>>(points2, W1);
    h1_mma<<<dim3(N1 / 128, C1 / 128, BB * GG), 256>>>(points1, W1, b1);
    bnstats_kernel<<<dim3(C1, GG), 256>>>(nullptr, gamma1, beta1, 0);
    gemm2_mma<<<dim3(N1 / 128, C2 / 128, BB * GG), 256>>>(W2, b2, out);
    bnstats_kernel<<<dim3(C2, GG), 256>>>(out, gamma2, beta2, 1);
    bnfinal_kernel<<<(BB * C2 * NTOT) / 4 / 256, 256>>>(out);
}

// round 7
// speedup vs baseline: 2.3647x; 1.1563x over previous
#include <cuda_runtime.h>
#include <cuda_fp16.h>
#include <cstdint>

// Problem constants (fixed by setup_inputs)
#define BB 2
#define GG 16
#define N1 4096
#define S1 1024
#define NTOT 65536   // GG*N1
#define STOT 16384   // GG*S1
#define D1 128
#define D2 256
#define C1 256
#define C2 256
#define INCH 384
#define BN_CNT 8192  // BB*N1 samples per (segment, channel)

// -------- device scratch (no allocations allowed) --------
__device__ float g_Y2t[BB * GG][S1][C1];       // 33.5 MB: (W1b @ p2)^T per segment
__device__ int   g_idx[BB * GG][N1][3];
__device__ float g_w[BB * GG][N1][3];
__device__ float g_h1[BB][C1][NTOT];           // 134 MB: layer-1 pre-activation
__device__ float g_scale1[GG][C1];
__device__ float g_shift1[GG][C1];
__device__ float g_scale2[GG][C2];
__device__ float g_shift2[GG][C2];

// -------- fp16 helpers --------
// pack two fp32 -> f16x2 (lo in low half)
__device__ __forceinline__ uint32_t f2h2(float lo, float hi) {
    uint32_t d;
    asm("cvt.rn.f16x2.f32 %0, %1, %2;" : "=r"(d) : "f"(hi), "f"(lo));
    return d;
}

__device__ __forceinline__ void hmma(float c[4], const uint32_t a[4],
                                     uint32_t b0, uint32_t b1) {
    asm volatile(
        "mma.sync.aligned.m16n8k16.row.col.f32.f16.f16.f32 "
        "{%0,%1,%2,%3},{%4,%5,%6,%7},{%8,%9},{%0,%1,%2,%3};"
        : "+f"(c[0]), "+f"(c[1]), "+f"(c[2]), "+f"(c[3])
        : "r"(a[0]), "r"(a[1]), "r"(a[2]), "r"(a[3]), "r"(b0), "r"(b1));
}

// A-fragment via ldmatrix.x4.trans from As[k][m] (half, pitch 136)
// B-fragment via LDS.32 from Bs[n][k] (half, pitch 24)
// Warp tile 64m x 32n, one k16 step per stage. C layout same as tf32 path.
__device__ __forceinline__ void compute_stage(
    const __half (*As)[136], const __half (*Bs)[24],
    float acc[4][4][4], int wm, int wn, int g, int tg, int lane)
{
    const int q  = lane >> 3, r = lane & 7;
    const int mq = (q & 1) * 8;
    const int kq = (q >> 1) * 8;
    uint32_t af[4][4];
    #pragma unroll
    for (int i = 0; i < 4; i++) {
        const int m = wm * 64 + i * 16;
        uint32_t sa = (uint32_t)__cvta_generic_to_shared(&As[kq + r][m + mq]);
        asm volatile(
            "ldmatrix.sync.aligned.m8n8.x4.trans.shared.b16 {%0,%1,%2,%3}, [%4];"
            : "=r"(af[i][0]), "=r"(af[i][1]), "=r"(af[i][2]), "=r"(af[i][3])
            : "r"(sa));
    }
    #pragma unroll
    for (int j = 0; j < 4; j++) {
        const int n = wn * 32 + j * 8 + g;
        const uint32_t b0 = *(const uint32_t*)&Bs[n][2 * tg];
        const uint32_t b1 = *(const uint32_t*)&Bs[n][2 * tg + 8];
        #pragma unroll
        for (int i = 0; i < 4; i++)
            hmma(acc[i][j], af[i], b0, b1);
    }
}

// ============================================================
// K1: 3-NN + inverse-distance weights (fp32, unchanged).
// ============================================================
__global__ __launch_bounds__(256) void knn_kernel(
    const float* __restrict__ xyz1, const float* __restrict__ xyz2)
{
    __shared__ float sx[S1], sy[S1], sz[S1];
    const int bg = blockIdx.y;
    const int b = bg >> 4, g = bg & 15;
    const float* x2 = xyz2 + (size_t)b * 3 * STOT + g * S1;
    for (int s = threadIdx.x; s < S1; s += 256) {
        sx[s] = x2[s];
        sy[s] = x2[STOT + s];
        sz[s] = x2[2 * STOT + s];
    }
    __syncthreads();

    const int n = blockIdx.x * 256 + threadIdx.x;
    const float* x1 = xyz1 + (size_t)b * 3 * NTOT + g * N1 + n;
    const float qx = x1[0], qy = x1[NTOT], qz = x1[2 * NTOT];

    float d0 = 3.4e38f, d1 = 3.4e38f, d2 = 3.4e38f;
    int i0 = 0, i1 = 0, i2 = 0;
    #pragma unroll 4
    for (int s = 0; s < S1; s++) {
        const float dx = qx - sx[s];
        const float dy = qy - sy[s];
        const float dz = qz - sz[s];
        const float d = fmaf(dx, dx, fmaf(dy, dy, dz * dz));
        if (d < d2) {
            if (d < d1) {
                if (d < d0) { d2 = d1; i2 = i1; d1 = d0; i1 = i0; d0 = d; i0 = s; }
                else        { d2 = d1; i2 = i1; d1 = d;  i1 = s; }
            } else          { d2 = d;  i2 = s; }
        }
    }
    float w0 = 1.0f / (d0 + 1e-8f);
    float w1 = 1.0f / (d1 + 1e-8f);
    float w2 = 1.0f / (d2 + 1e-8f);
    const float inv = 1.0f / (w0 + w1 + w2);
    g_idx[bg][n][0] = i0; g_idx[bg][n][1] = i1; g_idx[bg][n][2] = i2;
    g_w[bg][n][0] = w0 * inv; g_w[bg][n][1] = w1 * inv; g_w[bg][n][2] = w2 * inv;
}

// Staging helpers: per stage, 256 threads move A(16k x 128m fp32) and
// B(128n x 16k fp32) into half smem.
//   A: v=0,1: k=(t>>5)+8v, m=(t&31)*4   (src m-contiguous)
//   B: v=0,1: n=(t>>2)+64v, k=(t&3)*4   (src k-contiguous)
#define STAGE_STORE(Asb, Bsb, PA, PB)                                   \
    {                                                                   \
        _Pragma("unroll")                                               \
        for (int v = 0; v < 2; v++) {                                   \
            const int ka = (tid >> 5) + v * 8, ma = (tid & 31) * 4;     \
            uint2 h;                                                    \
            h.x = f2h2(PA[v].x, PA[v].y);                               \
            h.y = f2h2(PA[v].z, PA[v].w);                               \
            *(uint2*)&Asb[ka][ma] = h;                                  \
            const int nb = (tid >> 2) + v * 64, kb = (tid & 3) * 4;     \
            uint2 hb;                                                   \
            hb.x = f2h2(PB[v].x, PB[v].y);                              \
            hb.y = f2h2(PB[v].z, PB[v].w);                              \
            *(uint2*)&Bsb[nb][kb] = hb;                                 \
        }                                                               \
    }

// ============================================================
// K2: Y2t[bg][s][o] = sum_c p2[b][c][gS1+s] * W1[o][128+c]   (fp16 MMA)
// grid = (S1/128=8, C1/128=2, 32), K=256
// ============================================================
__global__ __launch_bounds__(256, 2) void y2t_mma(
    const float* __restrict__ p2, const float* __restrict__ W1)
{
    __shared__ __half As[2][16][136];
    __shared__ __half Bs[2][128][24];
    const int m0 = blockIdx.x * 128, n0 = blockIdx.y * 128;
    const int bg = blockIdx.z, b = bg >> 4, gg = bg & 15;
    const int tid = threadIdx.x, lane = tid & 31, wid = tid >> 5;
    const int wm = wid & 1, wn = wid >> 1, g = lane >> 2, tg = lane & 3;

    const float* Ab = p2 + (size_t)b * D2 * STOT + gg * S1 + m0;
    const float* Bb = W1 + 128 + (size_t)n0 * INCH;

    float acc[4][4][4] = {};
    float4 pa[2], pb[2];
    #pragma unroll
    for (int v = 0; v < 2; v++) {
        pa[v] = *(const float4*)(Ab + (size_t)((tid >> 5) + v * 8) * STOT + (tid & 31) * 4);
        pb[v] = *(const float4*)(Bb + (size_t)((tid >> 2) + v * 64) * INCH + (tid & 3) * 4);
    }
    int buf = 0;
    for (int kt = 0; kt < 256; kt += 16) {
        STAGE_STORE(As[buf], Bs[buf], pa, pb);
        __syncthreads();
        if (kt + 16 < 256) {
            #pragma unroll
            for (int v = 0; v < 2; v++) {
                pa[v] = *(const float4*)(Ab + (size_t)(kt + 16 + (tid >> 5) + v * 8) * STOT + (tid & 31) * 4);
                pb[v] = *(const float4*)(Bb + (size_t)((tid >> 2) + v * 64) * INCH + kt + 16 + (tid & 3) * 4);
            }
        }
        compute_stage(As[buf], Bs[buf], acc, wm, wn, g, tg, lane);
        buf ^= 1;
    }
    #pragma unroll
    for (int i = 0; i < 4; i++) {
        const int s = m0 + wm * 64 + i * 16 + g;
        #pragma unroll
        for (int j = 0; j < 4; j++) {
            const int o = n0 + wn * 32 + j * 8 + 2 * tg;
            *(float2*)&g_Y2t[bg][s][o]     = make_float2(acc[i][j][0], acc[i][j][1]);
            *(float2*)&g_Y2t[bg][s + 8][o] = make_float2(acc[i][j][2], acc[i][j][3]);
        }
    }
}

// ============================================================
// K3: h1_pre = W1a @ p1 (fp16 MMA, K=128) + fp32 interp-gather + bias.
// grid = (N1/128=32, 2, 32)
// ============================================================
__global__ __launch_bounds__(256, 2) void h1_mma(
    const float* __restrict__ p1, const float* __restrict__ W1,
    const float* __restrict__ b1)
{
    __shared__ __half As[2][16][136];
    __shared__ __half Bs[2][128][24];
    const int m0 = blockIdx.x * 128, n0 = blockIdx.y * 128;
    const int bg = blockIdx.z, b = bg >> 4, gg = bg & 15;
    const int tid = threadIdx.x, lane = tid & 31, wid = tid >> 5;
    const int wm = wid & 1, wn = wid >> 1, g = lane >> 2, tg = lane & 3;

    const float* Ab = p1 + (size_t)b * D1 * NTOT + gg * N1 + m0;
    const float* Bb = W1 + (size_t)n0 * INCH;

    float acc[4][4][4] = {};
    float4 pa[2], pb[2];
    #pragma unroll
    for (int v = 0; v < 2; v++) {
        pa[v] = *(const float4*)(Ab + (size_t)((tid >> 5) + v * 8) * NTOT + (tid & 31) * 4);
        pb[v] = *(const float4*)(Bb + (size_t)((tid >> 2) + v * 64) * INCH + (tid & 3) * 4);
    }
    int buf = 0;
    for (int kt = 0; kt < 128; kt += 16) {
        STAGE_STORE(As[buf], Bs[buf], pa, pb);
        __syncthreads();
        if (kt + 16 < 128) {
            #pragma unroll
            for (int v = 0; v < 2; v++) {
                pa[v] = *(const float4*)(Ab + (size_t)(kt + 16 + (tid >> 5) + v * 8) * NTOT + (tid & 31) * 4);
                pb[v] = *(const float4*)(Bb + (size_t)((tid >> 2) + v * 64) * INCH + kt + 16 + (tid & 3) * 4);
            }
        }
        compute_stage(As[buf], Bs[buf], acc, wm, wn, g, tg, lane);
        buf ^= 1;
    }

    // fp32 epilogue: 3-NN interpolation of precomputed Y2t, + bias, store to g_h1
    #pragma unroll
    for (int i = 0; i < 4; i++) {
        const int rA = m0 + wm * 64 + i * 16 + g;
        const int rB = rA + 8;
        int   iA[3], iB[3];
        float wA[3], wB[3];
        #pragma unroll
        for (int k = 0; k < 3; k++) {
            iA[k] = g_idx[bg][rA][k]; wA[k] = g_w[bg][rA][k];
            iB[k] = g_idx[bg][rB][k]; wB[k] = g_w[bg][rB][k];
        }
        #pragma unroll
        for (int j = 0; j < 4; j++) {
            const int o = n0 + wn * 32 + j * 8 + 2 * tg;
            float c0 = acc[i][j][0], c1 = acc[i][j][1];
            float c2 = acc[i][j][2], c3 = acc[i][j][3];
            #pragma unroll
            for (int k = 0; k < 3; k++) {
                const float2 yA = *(const float2*)&g_Y2t[bg][iA[k]][o];
                c0 = fmaf(wA[k], yA.x, c0); c1 = fmaf(wA[k], yA.y, c1);
                const float2 yB = *(const float2*)&g_Y2t[bg][iB[k]][o];
                c2 = fmaf(wB[k], yB.x, c2); c3 = fmaf(wB[k], yB.y, c3);
            }
            const float2 bo = *(const float2*)(b1 + o);
            g_h1[b][o][gg * N1 + rA]     = c0 + bo.x;
            g_h1[b][o + 1][gg * N1 + rA] = c1 + bo.y;
            g_h1[b][o][gg * N1 + rB]     = c2 + bo.x;
            g_h1[b][o + 1][gg * N1 + rB] = c3 + bo.y;
        }
    }
}

// ============================================================
// K4/K6: per-(segment, channel) BN stats -> (scale, shift). Unchanged.
// ============================================================
__global__ __launch_bounds__(256) void bnstats_kernel(
    const float* __restrict__ x2, const float* __restrict__ gamma,
    const float* __restrict__ beta, int layer)
{
    const int c = blockIdx.x, g = blockIdx.y, tid = threadIdx.x;
    const float* x = layer ? x2 : &g_h1[0][0][0];
    float s = 0.f, q = 0.f;
    for (int b = 0; b < BB; b++) {
        const float4* p = (const float4*)(x + ((size_t)(b * 256 + c)) * NTOT + (size_t)g * N1);
        for (int t = tid; t < N1 / 4; t += 256) {
            const float4 v = p[t];
            s += (v.x + v.y) + (v.z + v.w);
            q = fmaf(v.x, v.x, q); q = fmaf(v.y, v.y, q);
            q = fmaf(v.z, v.z, q); q = fmaf(v.w, v.w, q);
        }
    }
    __shared__ float rs[256], rq[256];
    rs[tid] = s; rq[tid] = q;
    __syncthreads();
    for (int off = 128; off; off >>= 1) {
        if (tid < off) { rs[tid] += rs[tid + off]; rq[tid] += rq[tid + off]; }
        __syncthreads();
    }
    if (tid == 0) {
        const float inv = 1.0f / (float)BN_CNT;
        const float mean = rs[0] * inv;
        const float var = rq[0] * inv - mean * mean;
        const float sc = gamma[c] * rsqrtf(var + 1e-5f);
        const float sh = beta[c] - mean * sc;
        if (layer == 0) { g_scale1[g][c] = sc; g_shift1[g][c] = sh; }
        else            { g_scale2[g][c] = sc; g_shift2[g][c] = sh; }
    }
}

// ============================================================
// K5: h2_pre = W2 @ relu(bn1(h1_pre)) + b2  (fp16 MMA; BN1+ReLU fused
// into A-tile conversion). grid = (32, 2, 32). Writes d_out.
// ============================================================
__global__ __launch_bounds__(256, 2) void gemm2_mma(
    const float* __restrict__ W2, const float* __restrict__ b2,
    float* __restrict__ out)
{
    __shared__ __half As[2][16][136];
    __shared__ __half Bs[2][128][24];
    const int m0 = blockIdx.x * 128, n0 = blockIdx.y * 128;
    const int bg = blockIdx.z, b = bg >> 4, gg = bg & 15;
    const int tid = threadIdx.x, lane = tid & 31, wid = tid >> 5;
    const int wm = wid & 1, wn = wid >> 1, g = lane >> 2, tg = lane & 3;

    const float* Ab = &g_h1[b][0][gg * N1 + m0];
    const float* Bb = W2 + (size_t)n0 * 256;

    float acc[4][4][4] = {};
    float4 pa[2], pb[2];
    float psc[2], psh[2];
    #pragma unroll
    for (int v = 0; v < 2; v++) {
        const int kr = (tid >> 5) + v * 8;
        pa[v] = *(const float4*)(Ab + (size_t)kr * NTOT + (tid & 31) * 4);
        pb[v] = *(const float4*)(Bb + (size_t)((tid >> 2) + v * 64) * 256 + (tid & 3) * 4);
        psc[v] = g_scale1[gg][kr];
        psh[v] = g_shift1[gg][kr];
    }
    int buf = 0;
    for (int kt = 0; kt < 256; kt += 16) {
        // BN1 + ReLU fused into A conversion
        float4 qa[2];
        #pragma unroll
        for (int v = 0; v < 2; v++) {
            qa[v].x = fmaxf(fmaf(pa[v].x, psc[v], psh[v]), 0.f);
            qa[v].y = fmaxf(fmaf(pa[v].y, psc[v], psh[v]), 0.f);
            qa[v].z = fmaxf(fmaf(pa[v].z, psc[v], psh[v]), 0.f);
            qa[v].w = fmaxf(fmaf(pa[v].w, psc[v], psh[v]), 0.f);
        }
        STAGE_STORE(As[buf], Bs[buf], qa, pb);
        __syncthreads();
        if (kt + 16 < 256) {
            #pragma unroll
            for (int v = 0; v < 2; v++) {
                const int c = kt + 16 + (tid >> 5) + v * 8;
                pa[v] = *(const float4*)(Ab + (size_t)c * NTOT + (tid & 31) * 4);
                pb[v] = *(const float4*)(Bb + (size_t)((tid >> 2) + v * 64) * 256 + kt + 16 + (tid & 3) * 4);
                psc[v] = g_scale1[gg][c];
                psh[v] = g_shift1[gg][c];
            }
        }
        compute_stage(As[buf], Bs[buf], acc, wm, wn, g, tg, lane);
        buf ^= 1;
    }
    #pragma unroll
    for (int i = 0; i < 4; i++) {
        const int rA = m0 + wm * 64 + i * 16 + g;
        const int rB = rA + 8;
        #pragma unroll
        for (int j = 0; j < 4; j++) {
            const int o = n0 + wn * 32 + j * 8 + 2 * tg;
            const float2 bo = *(const float2*)(b2 + o);
            out[((size_t)(b * 256 + o)) * NTOT + gg * N1 + rA]     = acc[i][j][0] + bo.x;
            out[((size_t)(b * 256 + o + 1)) * NTOT + gg * N1 + rA] = acc[i][j][1] + bo.y;
            out[((size_t)(b * 256 + o)) * NTOT + gg * N1 + rB]     = acc[i][j][2] + bo.x;
            out[((size_t)(b * 256 + o + 1)) * NTOT + gg * N1 + rB] = acc[i][j][3] + bo.y;
        }
    }
}

// ============================================================
// K7: in-place BN2 + ReLU on d_out. Unchanged.
// ============================================================
__global__ __launch_bounds__(256) void bnfinal_kernel(float* __restrict__ out)
{
    const size_t f4 = (size_t)blockIdx.x * 256 + threadIdx.x;
    const size_t f = f4 * 4;
    const int o = (int)((f >> 16) & 255);
    const int g = (int)((f >> 12) & 15);
    const float sc = g_scale2[g][o];
    const float sh = g_shift2[g][o];
    float4 v = ((float4*)out)[f4];
    v.x = fmaxf(fmaf(v.x, sc, sh), 0.f);
    v.y = fmaxf(fmaf(v.y, sc, sh), 0.f);
    v.z = fmaxf(fmaf(v.z, sc, sh), 0.f);
    v.w = fmaxf(fmaf(v.w, sc, sh), 0.f);
    ((float4*)out)[f4] = v;
}

// ============================================================
extern "C" void kernel_launch(void* const* d_in, const int* in_sizes, int n_in,
                              void* d_out, int out_size)
{
    (void)in_sizes; (void)n_in; (void)out_size;
    const float* xyz1    = (const float*)d_in[0];
    const float* points1 = (const float*)d_in[1];
    const float* xyz2    = (const float*)d_in[3];
    const float* points2 = (const float*)d_in[4];
    const float* W1      = (const float*)d_in[6];
    const float* b1      = (const float*)d_in[7];
    const float* gamma1  = (const float*)d_in[8];
    const float* beta1   = (const float*)d_in[9];
    const float* W2      = (const float*)d_in[10];
    const float* b2      = (const float*)d_in[11];
    const float* gamma2  = (const float*)d_in[12];
    const float* beta2   = (const float*)d_in[13];
    float* out = (float*)d_out;

    knn_kernel<<<dim3(N1 / 256, BB * GG), 256>>>(xyz1, xyz2);
    y2t_mma<<<dim3(S1 / 128, C1 / 128, BB * GG), 256>>>(points2, W1);
    h1_mma<<<dim3(N1 / 128, C1 / 128, BB * GG), 256>>>(points1, W1, b1);
    bnstats_kernel<<<dim3(C1, GG), 256>>>(nullptr, gamma1, beta1, 0);
    gemm2_mma<<<dim3(N1 / 128, C2 / 128, BB * GG), 256>>>(W2, b2, out);
    bnstats_kernel<<<dim3(C2, GG), 256>>>(out, gamma2, beta2, 1);
    bnfinal_kernel<<<(BB * C2 * NTOT) / 4 / 256, 256>>>(out);
}

// round 8
// speedup vs baseline: 2.6121x; 1.1046x over previous
#include <cuda_runtime.h>
#include <cuda_fp16.h>
#include <cstdint>

// Problem constants (fixed by setup_inputs)
#define BB 2
#define GG 16
#define N1 4096
#define S1 1024
#define NTOT 65536   // GG*N1
#define STOT 16384   // GG*S1
#define D1 128
#define D2 256
#define C1 256
#define C2 256
#define INCH 384
#define BN_CNT 8192  // BB*N1 samples per (segment, channel)
#define NSLOT 128    // BN partial slots per (segment, channel): b(2) x mtile(32) x wm(2)

// -------- device scratch (no allocations allowed) --------
__device__ float  g_Y2t[BB * GG][S1][C1];      // 33.5 MB
__device__ int    g_idx[BB * GG][N1][3];
__device__ float  g_w[BB * GG][N1][3];
__device__ __half g_h1h[BB][C1][NTOT];         // 67 MB: layer-1 pre-act (fp16)
__device__ __half g_h2h[BB][C2][NTOT];         // 67 MB: layer-2 pre-act (fp16)
__device__ float  g_ps[2][GG][C1][NSLOT];      // BN partial sums
__device__ float  g_pq[2][GG][C1][NSLOT];      // BN partial sum-of-squares
__device__ float  g_scale1[GG][C1];
__device__ float  g_shift1[GG][C1];
__device__ float  g_scale2[GG][C2];
__device__ float  g_shift2[GG][C2];

// -------- fp16 helpers --------
__device__ __forceinline__ uint32_t f2h2(float lo, float hi) {
    uint32_t d;
    asm("cvt.rn.f16x2.f32 %0, %1, %2;" : "=r"(d) : "f"(hi), "f"(lo));
    return d;
}

__device__ __forceinline__ void hmma(float c[4], const uint32_t a[4],
                                     uint32_t b0, uint32_t b1) {
    asm volatile(
        "mma.sync.aligned.m16n8k16.row.col.f32.f16.f16.f32 "
        "{%0,%1,%2,%3},{%4,%5,%6,%7},{%8,%9},{%0,%1,%2,%3};"
        : "+f"(c[0]), "+f"(c[1]), "+f"(c[2]), "+f"(c[3])
        : "r"(a[0]), "r"(a[1]), "r"(a[2]), "r"(a[3]), "r"(b0), "r"(b1));
}

// A-fragment via ldmatrix.x4.trans from As[k][m] (half, pitch 136)
// B-fragment via LDS.32 from Bs[n][k] (half, pitch 24)
__device__ __forceinline__ void compute_stage(
    const __half (*As)[136], const __half (*Bs)[24],
    float acc[4][4][4], int wm, int wn, int g, int tg, int lane)
{
    const int q  = lane >> 3, r = lane & 7;
    const int mq = (q & 1) * 8;
    const int kq = (q >> 1) * 8;
    uint32_t af[4][4];
    #pragma unroll
    for (int i = 0; i < 4; i++) {
        const int m = wm * 64 + i * 16;
        uint32_t sa = (uint32_t)__cvta_generic_to_shared(&As[kq + r][m + mq]);
        asm volatile(
            "ldmatrix.sync.aligned.m8n8.x4.trans.shared.b16 {%0,%1,%2,%3}, [%4];"
            : "=r"(af[i][0]), "=r"(af[i][1]), "=r"(af[i][2]), "=r"(af[i][3])
            : "r"(sa));
    }
    #pragma unroll
    for (int j = 0; j < 4; j++) {
        const int n = wn * 32 + j * 8 + g;
        const uint32_t b0 = *(const uint32_t*)&Bs[n][2 * tg];
        const uint32_t b1 = *(const uint32_t*)&Bs[n][2 * tg + 8];
        #pragma unroll
        for (int i = 0; i < 4; i++)
            hmma(acc[i][j], af[i], b0, b1);
    }
}

// Per-thread BN partial reduction over the warp's 64 rows, then one
// deterministic (non-atomic) store per (channel, slot).
__device__ __forceinline__ void epilogue_stats(
    float ssum[4][2], float sq[4][2], int layer, int gg, int n0,
    int wn, int lane, int slot)
{
    #pragma unroll
    for (int off = 4; off <= 16; off <<= 1) {
        #pragma unroll
        for (int j = 0; j < 4; j++) {
            ssum[j][0] += __shfl_xor_sync(0xffffffffu, ssum[j][0], off);
            ssum[j][1] += __shfl_xor_sync(0xffffffffu, ssum[j][1], off);
            sq[j][0]   += __shfl_xor_sync(0xffffffffu, sq[j][0], off);
            sq[j][1]   += __shfl_xor_sync(0xffffffffu, sq[j][1], off);
        }
    }
    if (lane < 4) {
        #pragma unroll
        for (int j = 0; j < 4; j++) {
            const int c = n0 + wn * 32 + j * 8 + 2 * lane;
            g_ps[layer][gg][c][slot]     = ssum[j][0];
            g_pq[layer][gg][c][slot]     = sq[j][0];
            g_ps[layer][gg][c + 1][slot] = ssum[j][1];
            g_pq[layer][gg][c + 1][slot] = sq[j][1];
        }
    }
}

// ============================================================
// K1: 3-NN + inverse-distance weights (fp32, unchanged).
// ============================================================
__global__ __launch_bounds__(256) void knn_kernel(
    const float* __restrict__ xyz1, const float* __restrict__ xyz2)
{
    __shared__ float sx[S1], sy[S1], sz[S1];
    const int bg = blockIdx.y;
    const int b = bg >> 4, g = bg & 15;
    const float* x2 = xyz2 + (size_t)b * 3 * STOT + g * S1;
    for (int s = threadIdx.x; s < S1; s += 256) {
        sx[s] = x2[s];
        sy[s] = x2[STOT + s];
        sz[s] = x2[2 * STOT + s];
    }
    __syncthreads();

    const int n = blockIdx.x * 256 + threadIdx.x;
    const float* x1 = xyz1 + (size_t)b * 3 * NTOT + g * N1 + n;
    const float qx = x1[0], qy = x1[NTOT], qz = x1[2 * NTOT];

    float d0 = 3.4e38f, d1 = 3.4e38f, d2 = 3.4e38f;
    int i0 = 0, i1 = 0, i2 = 0;
    #pragma unroll 4
    for (int s = 0; s < S1; s++) {
        const float dx = qx - sx[s];
        const float dy = qy - sy[s];
        const float dz = qz - sz[s];
        const float d = fmaf(dx, dx, fmaf(dy, dy, dz * dz));
        if (d < d2) {
            if (d < d1) {
                if (d < d0) { d2 = d1; i2 = i1; d1 = d0; i1 = i0; d0 = d; i0 = s; }
                else        { d2 = d1; i2 = i1; d1 = d;  i1 = s; }
            } else          { d2 = d;  i2 = s; }
        }
    }
    float w0 = 1.0f / (d0 + 1e-8f);
    float w1 = 1.0f / (d1 + 1e-8f);
    float w2 = 1.0f / (d2 + 1e-8f);
    const float inv = 1.0f / (w0 + w1 + w2);
    g_idx[bg][n][0] = i0; g_idx[bg][n][1] = i1; g_idx[bg][n][2] = i2;
    g_w[bg][n][0] = w0 * inv; g_w[bg][n][1] = w1 * inv; g_w[bg][n][2] = w2 * inv;
}

// Staging: 256 threads move A(16k x 128m fp32) and B(128n x 16k fp32) to half smem.
#define STAGE_STORE(Asb, Bsb, PA, PB)                                   \
    {                                                                   \
        _Pragma("unroll")                                               \
        for (int v = 0; v < 2; v++) {                                   \
            const int ka = (tid >> 5) + v * 8, ma = (tid & 31) * 4;     \
            uint2 h;                                                    \
            h.x = f2h2(PA[v].x, PA[v].y);                               \
            h.y = f2h2(PA[v].z, PA[v].w);                               \
            *(uint2*)&Asb[ka][ma] = h;                                  \
            const int nb = (tid >> 2) + v * 64, kb = (tid & 3) * 4;     \
            uint2 hb;                                                   \
            hb.x = f2h2(PB[v].x, PB[v].y);                              \
            hb.y = f2h2(PB[v].z, PB[v].w);                              \
            *(uint2*)&Bsb[nb][kb] = hb;                                 \
        }                                                               \
    }

// ============================================================
// K2: Y2t = (W1b @ p2)^T  (fp16 MMA, K=256). grid = (8, 2, 32)
// ============================================================
__global__ __launch_bounds__(256, 2) void y2t_mma(
    const float* __restrict__ p2, const float* __restrict__ W1)
{
    __shared__ __half As[2][16][136];
    __shared__ __half Bs[2][128][24];
    const int m0 = blockIdx.x * 128, n0 = blockIdx.y * 128;
    const int bg = blockIdx.z, b = bg >> 4, gg = bg & 15;
    const int tid = threadIdx.x, lane = tid & 31, wid = tid >> 5;
    const int wm = wid & 1, wn = wid >> 1, g = lane >> 2, tg = lane & 3;

    const float* Ab = p2 + (size_t)b * D2 * STOT + gg * S1 + m0;
    const float* Bb = W1 + 128 + (size_t)n0 * INCH;

    float acc[4][4][4] = {};
    float4 pa[2], pb[2];
    #pragma unroll
    for (int v = 0; v < 2; v++) {
        pa[v] = *(const float4*)(Ab + (size_t)((tid >> 5) + v * 8) * STOT + (tid & 31) * 4);
        pb[v] = *(const float4*)(Bb + (size_t)((tid >> 2) + v * 64) * INCH + (tid & 3) * 4);
    }
    int buf = 0;
    for (int kt = 0; kt < 256; kt += 16) {
        STAGE_STORE(As[buf], Bs[buf], pa, pb);
        __syncthreads();
        if (kt + 16 < 256) {
            #pragma unroll
            for (int v = 0; v < 2; v++) {
                pa[v] = *(const float4*)(Ab + (size_t)(kt + 16 + (tid >> 5) + v * 8) * STOT + (tid & 31) * 4);
                pb[v] = *(const float4*)(Bb + (size_t)((tid >> 2) + v * 64) * INCH + kt + 16 + (tid & 3) * 4);
            }
        }
        compute_stage(As[buf], Bs[buf], acc, wm, wn, g, tg, lane);
        buf ^= 1;
    }
    #pragma unroll
    for (int i = 0; i < 4; i++) {
        const int s = m0 + wm * 64 + i * 16 + g;
        #pragma unroll
        for (int j = 0; j < 4; j++) {
            const int o = n0 + wn * 32 + j * 8 + 2 * tg;
            *(float2*)&g_Y2t[bg][s][o]     = make_float2(acc[i][j][0], acc[i][j][1]);
            *(float2*)&g_Y2t[bg][s + 8][o] = make_float2(acc[i][j][2], acc[i][j][3]);
        }
    }
}

// ============================================================
// K3: h1_pre = W1a @ p1 + interp(Y2t) + b1 -> fp16 store + BN1 partials.
// grid = (32, 2, 32)
// ============================================================
__global__ __launch_bounds__(256, 2) void h1_mma(
    const float* __restrict__ p1, const float* __restrict__ W1,
    const float* __restrict__ b1)
{
    __shared__ __half As[2][16][136];
    __shared__ __half Bs[2][128][24];
    const int m0 = blockIdx.x * 128, n0 = blockIdx.y * 128;
    const int bg = blockIdx.z, b = bg >> 4, gg = bg & 15;
    const int tid = threadIdx.x, lane = tid & 31, wid = tid >> 5;
    const int wm = wid & 1, wn = wid >> 1, g = lane >> 2, tg = lane & 3;

    const float* Ab = p1 + (size_t)b * D1 * NTOT + gg * N1 + m0;
    const float* Bb = W1 + (size_t)n0 * INCH;

    float acc[4][4][4] = {};
    float4 pa[2], pb[2];
    #pragma unroll
    for (int v = 0; v < 2; v++) {
        pa[v] = *(const float4*)(Ab + (size_t)((tid >> 5) + v * 8) * NTOT + (tid & 31) * 4);
        pb[v] = *(const float4*)(Bb + (size_t)((tid >> 2) + v * 64) * INCH + (tid & 3) * 4);
    }
    int buf = 0;
    for (int kt = 0; kt < 128; kt += 16) {
        STAGE_STORE(As[buf], Bs[buf], pa, pb);
        __syncthreads();
        if (kt + 16 < 128) {
            #pragma unroll
            for (int v = 0; v < 2; v++) {
                pa[v] = *(const float4*)(Ab + (size_t)(kt + 16 + (tid >> 5) + v * 8) * NTOT + (tid & 31) * 4);
                pb[v] = *(const float4*)(Bb + (size_t)((tid >> 2) + v * 64) * INCH + kt + 16 + (tid & 3) * 4);
            }
        }
        compute_stage(As[buf], Bs[buf], acc, wm, wn, g, tg, lane);
        buf ^= 1;
    }

    // fp32 epilogue: interp(Y2t) + bias; fp16 store; BN1 partial stats.
    float ssum[4][2] = {}, sq[4][2] = {};
    #pragma unroll
    for (int i = 0; i < 4; i++) {
        const int rA = m0 + wm * 64 + i * 16 + g;
        const int rB = rA + 8;
        int   iA[3], iB[3];
        float wA[3], wB[3];
        #pragma unroll
        for (int k = 0; k < 3; k++) {
            iA[k] = g_idx[bg][rA][k]; wA[k] = g_w[bg][rA][k];
            iB[k] = g_idx[bg][rB][k]; wB[k] = g_w[bg][rB][k];
        }
        #pragma unroll
        for (int j = 0; j < 4; j++) {
            const int o = n0 + wn * 32 + j * 8 + 2 * tg;
            float c0 = acc[i][j][0], c1 = acc[i][j][1];
            float c2 = acc[i][j][2], c3 = acc[i][j][3];
            #pragma unroll
            for (int k = 0; k < 3; k++) {
                const float2 yA = *(const float2*)&g_Y2t[bg][iA[k]][o];
                c0 = fmaf(wA[k], yA.x, c0); c1 = fmaf(wA[k], yA.y, c1);
                const float2 yB = *(const float2*)&g_Y2t[bg][iB[k]][o];
                c2 = fmaf(wB[k], yB.x, c2); c3 = fmaf(wB[k], yB.y, c3);
            }
            const float2 bo = *(const float2*)(b1 + o);
            c0 += bo.x; c1 += bo.y; c2 += bo.x; c3 += bo.y;
            g_h1h[b][o][gg * N1 + rA]     = __float2half(c0);
            g_h1h[b][o + 1][gg * N1 + rA] = __float2half(c1);
            g_h1h[b][o][gg * N1 + rB]     = __float2half(c2);
            g_h1h[b][o + 1][gg * N1 + rB] = __float2half(c3);
            ssum[j][0] += c0 + c2; sq[j][0] += c0 * c0 + c2 * c2;
            ssum[j][1] += c1 + c3; sq[j][1] += c1 * c1 + c3 * c3;
        }
    }
    epilogue_stats(ssum, sq, 0, gg, n0, wn, lane, b * 64 + blockIdx.x * 2 + wm);
}

// ============================================================
// K4/K6: finish BN stats (deterministic tree over NSLOT partials).
// grid = (C, GG), block = NSLOT.
// ============================================================
__global__ __launch_bounds__(NSLOT) void bnfinish_kernel(
    const float* __restrict__ gamma, const float* __restrict__ beta, int layer)
{
    const int c = blockIdx.x, gg = blockIdx.y, tid = threadIdx.x;
    __shared__ float rs[NSLOT], rq[NSLOT];
    rs[tid] = g_ps[layer][gg][c][tid];
    rq[tid] = g_pq[layer][gg][c][tid];
    __syncthreads();
    for (int off = NSLOT / 2; off; off >>= 1) {
        if (tid < off) { rs[tid] += rs[tid + off]; rq[tid] += rq[tid + off]; }
        __syncthreads();
    }
    if (tid == 0) {
        const float inv = 1.0f / (float)BN_CNT;
        const float mean = rs[0] * inv;
        const float var = rq[0] * inv - mean * mean;
        const float sc = gamma[c] * rsqrtf(var + 1e-5f);
        const float sh = beta[c] - mean * sc;
        if (layer == 0) { g_scale1[gg][c] = sc; g_shift1[gg][c] = sh; }
        else            { g_scale2[gg][c] = sc; g_shift2[gg][c] = sh; }
    }
}

// ============================================================
// K5: h2_pre = W2 @ relu(bn1(h1)) + b2 -> fp16 store + BN2 partials.
// A read from fp16 g_h1h; BN1+ReLU fused into A staging. grid = (32, 2, 32)
// ============================================================
__global__ __launch_bounds__(256, 2) void gemm2_mma(
    const float* __restrict__ W2, const float* __restrict__ b2)
{
    __shared__ __half As[2][16][136];
    __shared__ __half Bs[2][128][24];
    const int m0 = blockIdx.x * 128, n0 = blockIdx.y * 128;
    const int bg = blockIdx.z, b = bg >> 4, gg = bg & 15;
    const int tid = threadIdx.x, lane = tid & 31, wid = tid >> 5;
    const int wm = wid & 1, wn = wid >> 1, g = lane >> 2, tg = lane & 3;

    const __half* Abh = &g_h1h[b][0][gg * N1 + m0];
    const float*  Bb  = W2 + (size_t)n0 * 256;

    float acc[4][4][4] = {};
    // A prefetch: one uint4 (8 halves) per thread per stage. k=tid>>4, m=(tid&15)*8
    const int ka = tid >> 4, ma = (tid & 15) * 8;
    uint4 pha = *(const uint4*)(Abh + (size_t)ka * NTOT + ma);
    float psc = g_scale1[gg][ka], psh = g_shift1[gg][ka];
    float4 pb[2];
    #pragma unroll
    for (int v = 0; v < 2; v++)
        pb[v] = *(const float4*)(Bb + (size_t)((tid >> 2) + v * 64) * 256 + (tid & 3) * 4);

    int buf = 0;
    for (int kt = 0; kt < 256; kt += 16) {
        // A: unpack fp16 -> BN1+ReLU in fp32 -> repack fp16
        {
            const __half2* hp = (const __half2*)&pha;
            uint4 st;
            uint32_t* sp = (uint32_t*)&st;
            #pragma unroll
            for (int u = 0; u < 4; u++) {
                float2 f = __half22float2(hp[u]);
                f.x = fmaxf(fmaf(f.x, psc, psh), 0.f);
                f.y = fmaxf(fmaf(f.y, psc, psh), 0.f);
                sp[u] = f2h2(f.x, f.y);
            }
            *(uint4*)&As[buf][ka][ma] = st;
        }
        // B: fp32 -> fp16
        #pragma unroll
        for (int v = 0; v < 2; v++) {
            const int nb = (tid >> 2) + v * 64, kb = (tid & 3) * 4;
            uint2 hb;
            hb.x = f2h2(pb[v].x, pb[v].y);
            hb.y = f2h2(pb[v].z, pb[v].w);
            *(uint2*)&Bs[buf][nb][kb] = hb;
        }
        __syncthreads();
        if (kt + 16 < 256) {
            const int c = kt + 16 + ka;
            pha = *(const uint4*)(Abh + (size_t)c * NTOT + ma);
            psc = g_scale1[gg][c];
            psh = g_shift1[gg][c];
            #pragma unroll
            for (int v = 0; v < 2; v++)
                pb[v] = *(const float4*)(Bb + (size_t)((tid >> 2) + v * 64) * 256 + kt + 16 + (tid & 3) * 4);
        }
        compute_stage(As[buf], Bs[buf], acc, wm, wn, g, tg, lane);
        buf ^= 1;
    }

    // Epilogue: +bias, fp16 store to g_h2h, BN2 partial stats.
    float ssum[4][2] = {}, sq[4][2] = {};
    #pragma unroll
    for (int i = 0; i < 4; i++) {
        const int rA = m0 + wm * 64 + i * 16 + g;
        const int rB = rA + 8;
        #pragma unroll
        for (int j = 0; j < 4; j++) {
            const int o = n0 + wn * 32 + j * 8 + 2 * tg;
            const float2 bo = *(const float2*)(b2 + o);
            const float c0 = acc[i][j][0] + bo.x;
            const float c1 = acc[i][j][1] + bo.y;
            const float c2 = acc[i][j][2] + bo.x;
            const float c3 = acc[i][j][3] + bo.y;
            g_h2h[b][o][gg * N1 + rA]     = __float2half(c0);
            g_h2h[b][o + 1][gg * N1 + rA] = __float2half(c1);
            g_h2h[b][o][gg * N1 + rB]     = __float2half(c2);
            g_h2h[b][o + 1][gg * N1 + rB] = __float2half(c3);
            ssum[j][0] += c0 + c2; sq[j][0] += c0 * c0 + c2 * c2;
            ssum[j][1] += c1 + c3; sq[j][1] += c1 * c1 + c3 * c3;
        }
    }
    epilogue_stats(ssum, sq, 1, gg, n0, wn, lane, b * 64 + blockIdx.x * 2 + wm);
}

// ============================================================
// K7: BN2 + ReLU: fp16 g_h2h -> fp32 d_out.
// ============================================================
__global__ __launch_bounds__(256) void bnfinal_kernel(float* __restrict__ out)
{
    const size_t f4 = (size_t)blockIdx.x * 256 + threadIdx.x;
    const size_t f = f4 * 4;
    const int o = (int)((f >> 16) & 255);
    const int g = (int)((f >> 12) & 15);
    const float sc = g_scale2[g][o];
    const float sh = g_shift2[g][o];
    const uint2 hraw = ((const uint2*)&g_h2h[0][0][0])[f4];
    const float2 f0 = __half22float2(*(const __half2*)&hraw.x);
    const float2 f1 = __half22float2(*(const __half2*)&hraw.y);
    float4 v;
    v.x = fmaxf(fmaf(f0.x, sc, sh), 0.f);
    v.y = fmaxf(fmaf(f0.y, sc, sh), 0.f);
    v.z = fmaxf(fmaf(f1.x, sc, sh), 0.f);
    v.w = fmaxf(fmaf(f1.y, sc, sh), 0.f);
    ((float4*)out)[f4] = v;
}

// ============================================================
extern "C" void kernel_launch(void* const* d_in, const int* in_sizes, int n_in,
                              void* d_out, int out_size)
{
    (void)in_sizes; (void)n_in; (void)out_size;
    const float* xyz1    = (const float*)d_in[0];
    const float* points1 = (const float*)d_in[1];
    const float* xyz2    = (const float*)d_in[3];
    const float* points2 = (const float*)d_in[4];
    const float* W1      = (const float*)d_in[6];
    const float* b1      = (const float*)d_in[7];
    const float* gamma1  = (const float*)d_in[8];
    const float* beta1   = (const float*)d_in[9];
    const float* W2      = (const float*)d_in[10];
    const float* b2      = (const float*)d_in[11];
    const float* gamma2  = (const float*)d_in[12];
    const float* beta2   = (const float*)d_in[13];
    float* out = (float*)d_out;

    knn_kernel<<<dim3(N1 / 256, BB * GG), 256>>>(xyz1, xyz2);
    y2t_mma<<<dim3(S1 / 128, C1 / 128, BB * GG), 256>>>(points2, W1);
    h1_mma<<<dim3(N1 / 128, C1 / 128, BB * GG), 256>>>(points1, W1, b1);
    bnfinish_kernel<<<dim3(C1, GG), NSLOT>>>(gamma1, beta1, 0);
    gemm2_mma<<<dim3(N1 / 128, C2 / 128, BB * GG), 256>>>(W2, b2);
    bnfinish_kernel<<<dim3(C2, GG), NSLOT>>>(gamma2, beta2, 1);
    bnfinal_kernel<<<(BB * C2 * NTOT) / 4 / 256, 256>>>(out);
}

// round 9
// speedup vs baseline: 2.6903x; 1.0299x over previous
#include <cuda_runtime.h>
#include <cuda_fp16.h>
#include <cstdint>

// Problem constants (fixed by setup_inputs)
#define BB 2
#define GG 16
#define N1 4096
#define S1 1024
#define NTOT 65536   // GG*N1
#define STOT 16384   // GG*S1
#define D1 128
#define D2 256
#define C1 256
#define C2 256
#define INCH 384
#define BN_CNT 8192  // BB*N1 samples per (segment, channel)
#define NSLOT 128    // BN partial slots per (segment, channel)

// -------- device scratch (no allocations allowed) --------
__device__ float  g_Y2t[BB * GG][S1][C1];      // 33.5 MB
__device__ int    g_idx[BB * GG][N1][3];
__device__ float  g_w[BB * GG][N1][3];
__device__ __half g_h1h[BB][C1][NTOT];         // 67 MB: layer-1 pre-act (fp16)
__device__ __half g_h2h[BB][C2][NTOT];         // 67 MB: layer-2 pre-act (fp16)
__device__ float  g_ps[2][GG][C1][NSLOT];      // BN partial sums
__device__ float  g_pq[2][GG][C1][NSLOT];      // BN partial sum-of-squares
__device__ float  g_scale1[GG][C1];
__device__ float  g_shift1[GG][C1];
__device__ float  g_scale2[GG][C2];
__device__ float  g_shift2[GG][C2];

// -------- fp16 helpers --------
__device__ __forceinline__ uint32_t f2h2(float lo, float hi) {
    uint32_t d;
    asm("cvt.rn.f16x2.f32 %0, %1, %2;" : "=r"(d) : "f"(hi), "f"(lo));
    return d;
}

__device__ __forceinline__ void hmma(float c[4], const uint32_t a[4],
                                     uint32_t b0, uint32_t b1) {
    asm volatile(
        "mma.sync.aligned.m16n8k16.row.col.f32.f16.f16.f32 "
        "{%0,%1,%2,%3},{%4,%5,%6,%7},{%8,%9},{%0,%1,%2,%3};"
        : "+f"(c[0]), "+f"(c[1]), "+f"(c[2]), "+f"(c[3])
        : "r"(a[0]), "r"(a[1]), "r"(a[2]), "r"(a[3]), "r"(b0), "r"(b1));
}

// A-fragment via ldmatrix.x4.trans from As[k][m] (half, pitch 136)
// B-fragment via LDS.32 from Bs[n][k] (half, pitch 24)
__device__ __forceinline__ void compute_stage(
    const __half (*As)[136], const __half (*Bs)[24],
    float acc[4][4][4], int wm, int wn, int g, int tg, int lane)
{
    const int q  = lane >> 3, r = lane & 7;
    const int mq = (q & 1) * 8;
    const int kq = (q >> 1) * 8;
    uint32_t af[4][4];
    #pragma unroll
    for (int i = 0; i < 4; i++) {
        const int m = wm * 64 + i * 16;
        uint32_t sa = (uint32_t)__cvta_generic_to_shared(&As[kq + r][m + mq]);
        asm volatile(
            "ldmatrix.sync.aligned.m8n8.x4.trans.shared.b16 {%0,%1,%2,%3}, [%4];"
            : "=r"(af[i][0]), "=r"(af[i][1]), "=r"(af[i][2]), "=r"(af[i][3])
            : "r"(sa));
    }
    #pragma unroll
    for (int j = 0; j < 4; j++) {
        const int n = wn * 32 + j * 8 + g;
        const uint32_t b0 = *(const uint32_t*)&Bs[n][2 * tg];
        const uint32_t b1 = *(const uint32_t*)&Bs[n][2 * tg + 8];
        #pragma unroll
        for (int i = 0; i < 4; i++)
            hmma(acc[i][j], af[i], b0, b1);
    }
}

// Per-thread BN partial reduction, then one deterministic store per slot.
__device__ __forceinline__ void epilogue_stats(
    float ssum[4][2], float sq[4][2], int layer, int gg, int n0,
    int wn, int lane, int slot)
{
    #pragma unroll
    for (int off = 4; off <= 16; off <<= 1) {
        #pragma unroll
        for (int j = 0; j < 4; j++) {
            ssum[j][0] += __shfl_xor_sync(0xffffffffu, ssum[j][0], off);
            ssum[j][1] += __shfl_xor_sync(0xffffffffu, ssum[j][1], off);
            sq[j][0]   += __shfl_xor_sync(0xffffffffu, sq[j][0], off);
            sq[j][1]   += __shfl_xor_sync(0xffffffffu, sq[j][1], off);
        }
    }
    if (lane < 4) {
        #pragma unroll
        for (int j = 0; j < 4; j++) {
            const int c = n0 + wn * 32 + j * 8 + 2 * lane;
            g_ps[layer][gg][c][slot]     = ssum[j][0];
            g_pq[layer][gg][c][slot]     = sq[j][0];
            g_ps[layer][gg][c + 1][slot] = ssum[j][1];
            g_pq[layer][gg][c + 1][slot] = sq[j][1];
        }
    }
}

// ============================================================
// K1: 3-NN + inverse-distance weights (fp32, unchanged).
// ============================================================
__global__ __launch_bounds__(256) void knn_kernel(
    const float* __restrict__ xyz1, const float* __restrict__ xyz2)
{
    __shared__ float sx[S1], sy[S1], sz[S1];
    const int bg = blockIdx.y;
    const int b = bg >> 4, g = bg & 15;
    const float* x2 = xyz2 + (size_t)b * 3 * STOT + g * S1;
    for (int s = threadIdx.x; s < S1; s += 256) {
        sx[s] = x2[s];
        sy[s] = x2[STOT + s];
        sz[s] = x2[2 * STOT + s];
    }
    __syncthreads();

    const int n = blockIdx.x * 256 + threadIdx.x;
    const float* x1 = xyz1 + (size_t)b * 3 * NTOT + g * N1 + n;
    const float qx = x1[0], qy = x1[NTOT], qz = x1[2 * NTOT];

    float d0 = 3.4e38f, d1 = 3.4e38f, d2 = 3.4e38f;
    int i0 = 0, i1 = 0, i2 = 0;
    #pragma unroll 4
    for (int s = 0; s < S1; s++) {
        const float dx = qx - sx[s];
        const float dy = qy - sy[s];
        const float dz = qz - sz[s];
        const float d = fmaf(dx, dx, fmaf(dy, dy, dz * dz));
        if (d < d2) {
            if (d < d1) {
                if (d < d0) { d2 = d1; i2 = i1; d1 = d0; i1 = i0; d0 = d; i0 = s; }
                else        { d2 = d1; i2 = i1; d1 = d;  i1 = s; }
            } else          { d2 = d;  i2 = s; }
        }
    }
    float w0 = 1.0f / (d0 + 1e-8f);
    float w1 = 1.0f / (d1 + 1e-8f);
    float w2 = 1.0f / (d2 + 1e-8f);
    const float inv = 1.0f / (w0 + w1 + w2);
    g_idx[bg][n][0] = i0; g_idx[bg][n][1] = i1; g_idx[bg][n][2] = i2;
    g_w[bg][n][0] = w0 * inv; g_w[bg][n][1] = w1 * inv; g_w[bg][n][2] = w2 * inv;
}

// Staging: 256 threads move A(16k x 128m fp32) and B(128n x 16k fp32) to half smem.
#define STAGE_STORE(Asb, Bsb, PA, PB)                                   \
    {                                                                   \
        _Pragma("unroll")                                               \
        for (int v = 0; v < 2; v++) {                                   \
            const int ka = (tid >> 5) + v * 8, ma = (tid & 31) * 4;     \
            uint2 h;                                                    \
            h.x = f2h2(PA[v].x, PA[v].y);                               \
            h.y = f2h2(PA[v].z, PA[v].w);                               \
            *(uint2*)&Asb[ka][ma] = h;                                  \
            const int nb = (tid >> 2) + v * 64, kb = (tid & 3) * 4;     \
            uint2 hb;                                                   \
            hb.x = f2h2(PB[v].x, PB[v].y);                              \
            hb.y = f2h2(PB[v].z, PB[v].w);                              \
            *(uint2*)&Bsb[nb][kb] = hb;                                 \
        }                                                               \
    }

// ============================================================
// K2: Y2t = (W1b @ p2)^T  (fp16 MMA, K=256, prefetch depth 2).
// grid = (8, 2, 32)
// ============================================================
__global__ __launch_bounds__(256, 2) void y2t_mma(
    const float* __restrict__ p2, const float* __restrict__ W1)
{
    __shared__ __half As[2][16][136];
    __shared__ __half Bs[2][128][24];
    const int m0 = blockIdx.x * 128, n0 = blockIdx.y * 128;
    const int bg = blockIdx.z, b = bg >> 4, gg = bg & 15;
    const int tid = threadIdx.x, lane = tid & 31, wid = tid >> 5;
    const int wm = wid & 1, wn = wid >> 1, g = lane >> 2, tg = lane & 3;

    const float* Ab = p2 + (size_t)b * D2 * STOT + gg * S1 + m0;
    const float* Bb = W1 + 128 + (size_t)n0 * INCH;

    float acc[4][4][4] = {};
    float4 pa[2][2], pb[2][2];
    #pragma unroll
    for (int s = 0; s < 2; s++)
        #pragma unroll
        for (int v = 0; v < 2; v++) {
            pa[s][v] = *(const float4*)(Ab + (size_t)(16 * s + (tid >> 5) + v * 8) * STOT + (tid & 31) * 4);
            pb[s][v] = *(const float4*)(Bb + (size_t)((tid >> 2) + v * 64) * INCH + 16 * s + (tid & 3) * 4);
        }
    #pragma unroll 2
    for (int s = 0; s < 16; s++) {
        const int set = s & 1;
        STAGE_STORE(As[set], Bs[set], pa[set], pb[set]);
        __syncthreads();
        if (s + 2 < 16) {
            const int kt = 16 * (s + 2);
            #pragma unroll
            for (int v = 0; v < 2; v++) {
                pa[set][v] = *(const float4*)(Ab + (size_t)(kt + (tid >> 5) + v * 8) * STOT + (tid & 31) * 4);
                pb[set][v] = *(const float4*)(Bb + (size_t)((tid >> 2) + v * 64) * INCH + kt + (tid & 3) * 4);
            }
        }
        compute_stage(As[set], Bs[set], acc, wm, wn, g, tg, lane);
        __syncthreads();
    }
    #pragma unroll
    for (int i = 0; i < 4; i++) {
        const int s = m0 + wm * 64 + i * 16 + g;
        #pragma unroll
        for (int j = 0; j < 4; j++) {
            const int o = n0 + wn * 32 + j * 8 + 2 * tg;
            *(float2*)&g_Y2t[bg][s][o]     = make_float2(acc[i][j][0], acc[i][j][1]);
            *(float2*)&g_Y2t[bg][s + 8][o] = make_float2(acc[i][j][2], acc[i][j][3]);
        }
    }
}

// ============================================================
// K3: h1_pre = W1a @ p1 + interp(Y2t) + b1 -> fp16 store + BN1 partials.
// (fp16 MMA, K=128, prefetch depth 2). grid = (32, 2, 32)
// ============================================================
__global__ __launch_bounds__(256, 2) void h1_mma(
    const float* __restrict__ p1, const float* __restrict__ W1,
    const float* __restrict__ b1)
{
    __shared__ __half As[2][16][136];
    __shared__ __half Bs[2][128][24];
    const int m0 = blockIdx.x * 128, n0 = blockIdx.y * 128;
    const int bg = blockIdx.z, b = bg >> 4, gg = bg & 15;
    const int tid = threadIdx.x, lane = tid & 31, wid = tid >> 5;
    const int wm = wid & 1, wn = wid >> 1, g = lane >> 2, tg = lane & 3;

    const float* Ab = p1 + (size_t)b * D1 * NTOT + gg * N1 + m0;
    const float* Bb = W1 + (size_t)n0 * INCH;

    float acc[4][4][4] = {};
    float4 pa[2][2], pb[2][2];
    #pragma unroll
    for (int s = 0; s < 2; s++)
        #pragma unroll
        for (int v = 0; v < 2; v++) {
            pa[s][v] = *(const float4*)(Ab + (size_t)(16 * s + (tid >> 5) + v * 8) * NTOT + (tid & 31) * 4);
            pb[s][v] = *(const float4*)(Bb + (size_t)((tid >> 2) + v * 64) * INCH + 16 * s + (tid & 3) * 4);
        }
    #pragma unroll 2
    for (int s = 0; s < 8; s++) {
        const int set = s & 1;
        STAGE_STORE(As[set], Bs[set], pa[set], pb[set]);
        __syncthreads();
        if (s + 2 < 8) {
            const int kt = 16 * (s + 2);
            #pragma unroll
            for (int v = 0; v < 2; v++) {
                pa[set][v] = *(const float4*)(Ab + (size_t)(kt + (tid >> 5) + v * 8) * NTOT + (tid & 31) * 4);
                pb[set][v] = *(const float4*)(Bb + (size_t)((tid >> 2) + v * 64) * INCH + kt + (tid & 3) * 4);
            }
        }
        compute_stage(As[set], Bs[set], acc, wm, wn, g, tg, lane);
        __syncthreads();
    }

    // fp32 epilogue: interp(Y2t) + bias; fp16 store; BN1 partial stats.
    float ssum[4][2] = {}, sq[4][2] = {};
    #pragma unroll
    for (int i = 0; i < 4; i++) {
        const int rA = m0 + wm * 64 + i * 16 + g;
        const int rB = rA + 8;
        int   iA[3], iB[3];
        float wA[3], wB[3];
        #pragma unroll
        for (int k = 0; k < 3; k++) {
            iA[k] = g_idx[bg][rA][k]; wA[k] = g_w[bg][rA][k];
            iB[k] = g_idx[bg][rB][k]; wB[k] = g_w[bg][rB][k];
        }
        #pragma unroll
        for (int j = 0; j < 4; j++) {
            const int o = n0 + wn * 32 + j * 8 + 2 * tg;
            float c0 = acc[i][j][0], c1 = acc[i][j][1];
            float c2 = acc[i][j][2], c3 = acc[i][j][3];
            #pragma unroll
            for (int k = 0; k < 3; k++) {
                const float2 yA = *(const float2*)&g_Y2t[bg][iA[k]][o];
                c0 = fmaf(wA[k], yA.x, c0); c1 = fmaf(wA[k], yA.y, c1);
                const float2 yB = *(const float2*)&g_Y2t[bg][iB[k]][o];
                c2 = fmaf(wB[k], yB.x, c2); c3 = fmaf(wB[k], yB.y, c3);
            }
            const float2 bo = *(const float2*)(b1 + o);
            c0 += bo.x; c1 += bo.y; c2 += bo.x; c3 += bo.y;
            g_h1h[b][o][gg * N1 + rA]     = __float2half(c0);
            g_h1h[b][o + 1][gg * N1 + rA] = __float2half(c1);
            g_h1h[b][o][gg * N1 + rB]     = __float2half(c2);
            g_h1h[b][o + 1][gg * N1 + rB] = __float2half(c3);
            ssum[j][0] += c0 + c2; sq[j][0] += c0 * c0 + c2 * c2;
            ssum[j][1] += c1 + c3; sq[j][1] += c1 * c1 + c3 * c3;
        }
    }
    epilogue_stats(ssum, sq, 0, gg, n0, wn, lane, b * 64 + blockIdx.x * 2 + wm);
}

// ============================================================
// K4/K6: finish BN stats (deterministic tree over NSLOT partials).
// ============================================================
__global__ __launch_bounds__(NSLOT) void bnfinish_kernel(
    const float* __restrict__ gamma, const float* __restrict__ beta, int layer)
{
    const int c = blockIdx.x, gg = blockIdx.y, tid = threadIdx.x;
    __shared__ float rs[NSLOT], rq[NSLOT];
    rs[tid] = g_ps[layer][gg][c][tid];
    rq[tid] = g_pq[layer][gg][c][tid];
    __syncthreads();
    for (int off = NSLOT / 2; off; off >>= 1) {
        if (tid < off) { rs[tid] += rs[tid + off]; rq[tid] += rq[tid + off]; }
        __syncthreads();
    }
    if (tid == 0) {
        const float inv = 1.0f / (float)BN_CNT;
        const float mean = rs[0] * inv;
        const float var = rq[0] * inv - mean * mean;
        const float sc = gamma[c] * rsqrtf(var + 1e-5f);
        const float sh = beta[c] - mean * sc;
        if (layer == 0) { g_scale1[gg][c] = sc; g_shift1[gg][c] = sh; }
        else            { g_scale2[gg][c] = sc; g_shift2[gg][c] = sh; }
    }
}

// ============================================================
// K5: h2_pre = W2 @ relu(bn1(h1)) + b2 -> fp16 store + BN2 partials.
// (fp16 MMA, K=256, prefetch depth 2). grid = (32, 2, 32)
// ============================================================
__global__ __launch_bounds__(256, 2) void gemm2_mma(
    const float* __restrict__ W2, const float* __restrict__ b2)
{
    __shared__ __half As[2][16][136];
    __shared__ __half Bs[2][128][24];
    const int m0 = blockIdx.x * 128, n0 = blockIdx.y * 128;
    const int bg = blockIdx.z, b = bg >> 4, gg = bg & 15;
    const int tid = threadIdx.x, lane = tid & 31, wid = tid >> 5;
    const int wm = wid & 1, wn = wid >> 1, g = lane >> 2, tg = lane & 3;

    const __half* Abh = &g_h1h[b][0][gg * N1 + m0];
    const float*  Bb  = W2 + (size_t)n0 * 256;

    float acc[4][4][4] = {};
    const int ka = tid >> 4, ma = (tid & 15) * 8;
    uint4 pha[2];
    float psc[2], psh[2];
    float4 pb[2][2];
    #pragma unroll
    for (int s = 0; s < 2; s++) {
        const int c = 16 * s + ka;
        pha[s] = *(const uint4*)(Abh + (size_t)c * NTOT + ma);
        psc[s] = g_scale1[gg][c];
        psh[s] = g_shift1[gg][c];
        #pragma unroll
        for (int v = 0; v < 2; v++)
            pb[s][v] = *(const float4*)(Bb + (size_t)((tid >> 2) + v * 64) * 256 + 16 * s + (tid & 3) * 4);
    }
    #pragma unroll 2
    for (int s = 0; s < 16; s++) {
        const int set = s & 1;
        // A: unpack fp16 -> BN1+ReLU in fp32 -> repack fp16
        {
            const __half2* hp = (const __half2*)&pha[set];
            uint4 st;
            uint32_t* sp = (uint32_t*)&st;
            #pragma unroll
            for (int u = 0; u < 4; u++) {
                float2 f = __half22float2(hp[u]);
                f.x = fmaxf(fmaf(f.x, psc[set], psh[set]), 0.f);
                f.y = fmaxf(fmaf(f.y, psc[set], psh[set]), 0.f);
                sp[u] = f2h2(f.x, f.y);
            }
            *(uint4*)&As[set][ka][ma] = st;
        }
        #pragma unroll
        for (int v = 0; v < 2; v++) {
            const int nb = (tid >> 2) + v * 64, kb = (tid & 3) * 4;
            uint2 hb;
            hb.x = f2h2(pb[set][v].x, pb[set][v].y);
            hb.y = f2h2(pb[set][v].z, pb[set][v].w);
            *(uint2*)&Bs[set][nb][kb] = hb;
        }
        __syncthreads();
        if (s + 2 < 16) {
            const int c = 16 * (s + 2) + ka;
            pha[set] = *(const uint4*)(Abh + (size_t)c * NTOT + ma);
            psc[set] = g_scale1[gg][c];
            psh[set] = g_shift1[gg][c];
            #pragma unroll
            for (int v = 0; v < 2; v++)
                pb[set][v] = *(const float4*)(Bb + (size_t)((tid >> 2) + v * 64) * 256 + 16 * (s + 2) + (tid & 3) * 4);
        }
        compute_stage(As[set], Bs[set], acc, wm, wn, g, tg, lane);
        __syncthreads();
    }

    // Epilogue: +bias, fp16 store to g_h2h, BN2 partial stats.
    float ssum[4][2] = {}, sq[4][2] = {};
    #pragma unroll
    for (int i = 0; i < 4; i++) {
        const int rA = m0 + wm * 64 + i * 16 + g;
        const int rB = rA + 8;
        #pragma unroll
        for (int j = 0; j < 4; j++) {
            const int o = n0 + wn * 32 + j * 8 + 2 * tg;
            const float2 bo = *(const float2*)(b2 + o);
            const float c0 = acc[i][j][0] + bo.x;
            const float c1 = acc[i][j][1] + bo.y;
            const float c2 = acc[i][j][2] + bo.x;
            const float c3 = acc[i][j][3] + bo.y;
            g_h2h[b][o][gg * N1 + rA]     = __float2half(c0);
            g_h2h[b][o + 1][gg * N1 + rA] = __float2half(c1);
            g_h2h[b][o][gg * N1 + rB]     = __float2half(c2);
            g_h2h[b][o + 1][gg * N1 + rB] = __float2half(c3);
            ssum[j][0] += c0 + c2; sq[j][0] += c0 * c0 + c2 * c2;
            ssum[j][1] += c1 + c3; sq[j][1] += c1 * c1 + c3 * c3;
        }
    }
    epilogue_stats(ssum, sq, 1, gg, n0, wn, lane, b * 64 + blockIdx.x * 2 + wm);
}

// ============================================================
// K7: BN2 + ReLU: fp16 g_h2h -> fp32 d_out.
// ============================================================
__global__ __launch_bounds__(256) void bnfinal_kernel(float* __restrict__ out)
{
    const size_t f4 = (size_t)blockIdx.x * 256 + threadIdx.x;
    const size_t f = f4 * 4;
    const int o = (int)((f >> 16) & 255);
    const int g = (int)((f >> 12) & 15);
    const float sc = g_scale2[g][o];
    const float sh = g_shift2[g][o];
    const uint2 hraw = ((const uint2*)&g_h2h[0][0][0])[f4];
    const float2 f0 = __half22float2(*(const __half2*)&hraw.x);
    const float2 f1 = __half22float2(*(const __half2*)&hraw.y);
    float4 v;
    v.x = fmaxf(fmaf(f0.x, sc, sh), 0.f);
    v.y = fmaxf(fmaf(f0.y, sc, sh), 0.f);
    v.z = fmaxf(fmaf(f1.x, sc, sh), 0.f);
    v.w = fmaxf(fmaf(f1.y, sc, sh), 0.f);
    ((float4*)out)[f4] = v;
}

// ============================================================
extern "C" void kernel_launch(void* const* d_in, const int* in_sizes, int n_in,
                              void* d_out, int out_size)
{
    (void)in_sizes; (void)n_in; (void)out_size;
    const float* xyz1    = (const float*)d_in[0];
    const float* points1 = (const float*)d_in[1];
    const float* xyz2    = (const float*)d_in[3];
    const float* points2 = (const float*)d_in[4];
    const float* W1      = (const float*)d_in[6];
    const float* b1      = (const float*)d_in[7];
    const float* gamma1  = (const float*)d_in[8];
    const float* beta1   = (const float*)d_in[9];
    const float* W2      = (const float*)d_in[10];
    const float* b2      = (const float*)d_in[11];
    const float* gamma2  = (const float*)d_in[12];
    const float* beta2   = (const float*)d_in[13];
    float* out = (float*)d_out;

    knn_kernel<<<dim3(N1 / 256, BB * GG), 256>>>(xyz1, xyz2);
    y2t_mma<<<dim3(S1 / 128, C1 / 128, BB * GG), 256>>>(points2, W1);
    h1_mma<<<dim3(N1 / 128, C1 / 128, BB * GG), 256>>>(points1, W1, b1);
    bnfinish_kernel<<<dim3(C1, GG), NSLOT>>>(gamma1, beta1, 0);
    gemm2_mma<<<dim3(N1 / 128, C2 / 128, BB * GG), 256>>>(W2, b2);
    bnfinish_kernel<<<dim3(C2, GG), NSLOT>>>(gamma2, beta2, 1);
    bnfinal_kernel<<<(BB * C2 * NTOT) / 4 / 256, 256>>>(out);
}